// round 10
// baseline (speedup 1.0000x reference)
#include <cuda_runtime.h>
#include <math.h>
#include <stdint.h>

#define Bc 4
#define Nc 64
#define Tc 384
#define Hc 256
#define Lc 3
#define NUc 500
#define KTOP 8
#define BT (Bc*Tc)   // 1536
#define NL (Nc*Lc)   // 192

// ---------------- scratch (device globals; no allocation allowed) ----------------
__device__ __align__(16) float g_A   [Hc*Hc];
__device__ __align__(16) float g_c   [Hc];
__device__ __align__(16) float g_Qk  [BT*Hc];
__device__ __align__(16) float g_dsum[BT*Hc];
__device__             float g_wsum[BT];
__device__ __align__(16) float g_lly [BT*Hc];
__device__ __align__(16) float g_h1  [BT*Hc];
__device__ __align__(16) float g_x   [BT*Hc];
__device__ __align__(16) float g_bias[Bc*NL];

__device__ __forceinline__ bool mask_read(const void* m, size_t i, int is_byte)
{
    if (is_byte) return ((const unsigned char*)m)[i] != 0;
    return ((const unsigned int*)m)[i] != 0u;   // int32 AND float32 (bit-pattern nonzero)
}

// ---------------- detprep: mask dtype detect + per-(b,e) bias table --------------
__global__ void detprep_kernel(const float* __restrict__ lrs,
                               const void* __restrict__ pm, const void* __restrict__ rm,
                               const int* __restrict__ target_id,
                               const int* __restrict__ peer_id,
                               const float* __restrict__ alpha_p,
                               float* __restrict__ biasTab)
{
    __shared__ unsigned s_g, s_o;
    if (threadIdx.x == 0) { s_g = 0u; s_o = 0u; }
    __syncthreads();
    const uint4* rm16 = (const uint4*)rm;
    const int n16 = 16384;  // scan first 256 KB of rank mask
    unsigned gt1 = 0u, off = 0u;
    for (int i = threadIdx.x; i < n16; i += blockDim.x) {
        uint4 v = rm16[i];
        unsigned w = v.x | v.y | v.z | v.w;
        gt1 |= w & 0xFEFEFEFEu;   // any byte value > 1 -> float32 words
        off |= w & 0xFFFFFF00u;   // nonzero byte at idx%4 != 0 -> uint8
    }
#pragma unroll
    for (int s = 16; s; s >>= 1) {
        gt1 |= __shfl_xor_sync(0xffffffffu, gt1, s);
        off |= __shfl_xor_sync(0xffffffffu, off, s);
    }
    if ((threadIdx.x & 31) == 0) {
        if (gt1) atomicOr(&s_g, 1u);
        if (off) atomicOr(&s_o, 1u);
    }
    __syncthreads();
    int ib = (s_g == 0u && s_o != 0u) ? 1 : 0;

    float alpha = *alpha_p;
    for (int idx = threadIdx.x; idx < Bc * NL; idx += blockDim.x) {
        int b = idx / NL, e = idx - b * NL;
        int n = e / Lc, l = e - n * Lc;
        int tgt = target_id[b], pid = peer_id[b * Nc + n];
        size_t offr = ((size_t)l * NUc + pid) * NUc + tgt;
        bool valid = mask_read(pm, b * Nc + n, ib) && mask_read(rm, offr, ib);
        biasTab[idx] = valid ? alpha * lrs[offr] : -INFINITY;
    }
}

// ---------------- 32x32x16 fp32 GEMM, 128 threads, 2x4/thread, double-buffered ---
// C[M,N] = scale * op(A)[M,K] @ op(B)[K,N] (+bias[n]*rowscale[m]) (+add[m,n]) (ELU)
// CVEC (A-gemm only): blockIdx.y==0 blocks emit cvec_out[n] = scale * sum_k cvec_in[k]*B[k][n]
template<bool A_T, bool B_T, bool DO_ELU, bool HAS_BIAS, bool HAS_SCALE, bool HAS_ADD, bool CVEC>
__global__ void gemm32(const float* __restrict__ A, const float* __restrict__ Bm,
                       const float* __restrict__ bias, const float* __restrict__ rowscale,
                       const float* __restrict__ addm, float* __restrict__ C,
                       const float* __restrict__ cvec_in, float* __restrict__ cvec_out,
                       int M, int N, int K, float scale)
{
    const int BK = 16;
    __shared__ __align__(16) float As[2][BK][36];
    __shared__ __align__(16) float Bs[2][BK][36];

    int tid = threadIdx.x;                 // 128 threads
    int m0 = blockIdx.y * 32, n0 = blockIdx.x * 32;
    int tx = tid & 7, ty = tid >> 3;       // tx 0..7 (cols of 4), ty 0..15 (rows of 2)

    // load indices (1 float4 per thread per tile)
    int aI0, aI1, bI0, bI1;
    if (!A_T) { aI0 = tid >> 2; aI1 = (tid & 3) << 2; }   // ar(0..31), ac{0,4,8,12}
    else      { aI0 = tid >> 3; aI1 = (tid & 7) << 2; }   // kr(0..15), mc(0..28)
    if (!B_T) { bI0 = tid >> 3; bI1 = (tid & 7) << 2; }   // kr(0..15), nc(0..28)
    else      { bI0 = tid >> 2; bI1 = (tid & 3) << 2; }   // nr(0..31), kc{0,4,8,12}

    float acc[2][4];
#pragma unroll
    for (int i = 0; i < 2; i++)
#pragma unroll
        for (int j = 0; j < 4; j++) acc[i][j] = 0.f;

    float cacc[4] = {0.f, 0.f, 0.f, 0.f};
    const bool do_cvec = CVEC && (blockIdx.y == 0) && (ty == 0);

    float4 va, vb;
    if (!A_T) va = *(const float4*)&A[(size_t)(m0 + aI0) * K + aI1];
    else      va = *(const float4*)&A[(size_t)aI0 * M + m0 + aI1];
    if (!B_T) vb = *(const float4*)&Bm[(size_t)bI0 * N + n0 + bI1];
    else      vb = *(const float4*)&Bm[(size_t)(n0 + bI0) * K + bI1];
    if (!A_T) { As[0][aI1+0][aI0]=va.x; As[0][aI1+1][aI0]=va.y; As[0][aI1+2][aI0]=va.z; As[0][aI1+3][aI0]=va.w; }
    else      { *(float4*)&As[0][aI0][aI1] = va; }
    if (!B_T) { *(float4*)&Bs[0][bI0][bI1] = vb; }
    else      { Bs[0][bI1+0][bI0]=vb.x; Bs[0][bI1+1][bI0]=vb.y; Bs[0][bI1+2][bI0]=vb.z; Bs[0][bI1+3][bI0]=vb.w; }
    __syncthreads();

    int buf = 0;
    for (int k0 = 0; k0 < K; k0 += BK) {
        bool has_next = (k0 + BK < K);
        if (has_next) {
            int kn = k0 + BK;
            if (!A_T) va = *(const float4*)&A[(size_t)(m0 + aI0) * K + kn + aI1];
            else      va = *(const float4*)&A[(size_t)(kn + aI0) * M + m0 + aI1];
            if (!B_T) vb = *(const float4*)&Bm[(size_t)(kn + bI0) * N + n0 + bI1];
            else      vb = *(const float4*)&Bm[(size_t)(n0 + bI0) * K + kn + bI1];
        }
#pragma unroll
        for (int kk = 0; kk < BK; kk++) {
            float2 a2 = *(const float2*)&As[buf][kk][ty << 1];
            float4 b4 = *(const float4*)&Bs[buf][kk][tx << 2];
            acc[0][0] += a2.x * b4.x; acc[0][1] += a2.x * b4.y;
            acc[0][2] += a2.x * b4.z; acc[0][3] += a2.x * b4.w;
            acc[1][0] += a2.y * b4.x; acc[1][1] += a2.y * b4.y;
            acc[1][2] += a2.y * b4.z; acc[1][3] += a2.y * b4.w;
            if (CVEC) {
                if (do_cvec) {
                    float wb = __ldg(&cvec_in[k0 + kk]);
                    cacc[0] += wb * b4.x; cacc[1] += wb * b4.y;
                    cacc[2] += wb * b4.z; cacc[3] += wb * b4.w;
                }
            }
        }
        if (has_next) {
            int s = buf ^ 1;
            if (!A_T) { As[s][aI1+0][aI0]=va.x; As[s][aI1+1][aI0]=va.y; As[s][aI1+2][aI0]=va.z; As[s][aI1+3][aI0]=va.w; }
            else      { *(float4*)&As[s][aI0][aI1] = va; }
            if (!B_T) { *(float4*)&Bs[s][bI0][bI1] = vb; }
            else      { Bs[s][bI1+0][bI0]=vb.x; Bs[s][bI1+1][bI0]=vb.y; Bs[s][bI1+2][bI0]=vb.z; Bs[s][bI1+3][bI0]=vb.w; }
        }
        __syncthreads();
        buf ^= 1;
    }

    if (CVEC) {
        if (do_cvec) {
            float4 cv = make_float4(cacc[0]*scale, cacc[1]*scale, cacc[2]*scale, cacc[3]*scale);
            *(float4*)&cvec_out[n0 + (tx << 2)] = cv;
        }
    }

#pragma unroll
    for (int i = 0; i < 2; i++) {
        int m = m0 + (ty << 1) + i;
        float rs = 1.f;
        if (HAS_SCALE) rs = rowscale[m];
        float4 outv;
        float* po = (float*)&outv;
#pragma unroll
        for (int j = 0; j < 4; j++) {
            int n = n0 + (tx << 2) + j;
            float v = acc[i][j] * scale;
            if (HAS_BIAS) v += bias[n] * rs;
            if (HAS_ADD)  v += addm[(size_t)m * N + n];
            if (DO_ELU)   v = (v > 0.f) ? v : expm1f(v);
            po[j] = v;
        }
        *(float4*)&C[(size_t)m * N + n0 + (tx << 2)] = outv;
    }
}

// ---------------- logits + parallel rank top-8 + weighted delta-sum --------------
__global__ void logits_kernel(const float* __restrict__ peer,
                              const float* __restrict__ biasTab,
                              const float* __restrict__ Qk,
                              float* __restrict__ dsum,
                              float* __restrict__ wsum)
{
    int bt = blockIdx.x;
    int b = bt / Tc, t = bt - b * Tc;
    int tid = threadIdx.x, lane = tid & 31, warp = tid >> 5;

    __shared__ __align__(16) float sQk[Hc];
    __shared__ float sbias[NL];
    __shared__ float sev[8][24];     // per-warp e-values
    __shared__ float scv[64];        // 8 warps x top-8 candidate values
    __shared__ int   scix[64];       // candidate flat-e indices
    __shared__ float swv[KTOP];      // global top-8 raw values
    __shared__ int   sidx[KTOP];

    if (tid < 64) ((float4*)sQk)[tid] = ((const float4*)(Qk + (size_t)bt * Hc))[tid];
    if (tid < NL) sbias[tid] = biasTab[b * NL + tid];
    __syncthreads();

    float4 q0 = ((const float4*)sQk)[lane];
    float4 q1 = ((const float4*)sQk)[lane + 32];
    const int lags[3] = {1, 5, 21};

    // dot phase: warp w handles e = w + 8j + 24r, j in 0..2, r in 0..7
#pragma unroll 1
    for (int r = 0; r < 8; r++) {
        int ebase = warp + 24 * r;
        float4 v0[3], v1[3];
        float acc[3];
#pragma unroll
        for (int j = 0; j < 3; j++) {
            int e = ebase + 8 * j;
            int n = e / Lc, l = e - n * Lc;
            int tr = t - lags[l]; if (tr < 0) tr = 0;
            const float4* row = (const float4*)(peer + (((size_t)b * Nc + n) * Tc + tr) * Hc);
            v0[j] = row[lane];
            v1[j] = row[lane + 32];
        }
#pragma unroll
        for (int j = 0; j < 3; j++) {
            acc[j] = v0[j].x*q0.x + v0[j].y*q0.y + v0[j].z*q0.z + v0[j].w*q0.w
                   + v1[j].x*q1.x + v1[j].y*q1.y + v1[j].z*q1.z + v1[j].w*q1.w;
        }
#pragma unroll
        for (int s = 16; s; s >>= 1) {
            acc[0] += __shfl_xor_sync(0xffffffffu, acc[0], s);
            acc[1] += __shfl_xor_sync(0xffffffffu, acc[1], s);
            acc[2] += __shfl_xor_sync(0xffffffffu, acc[2], s);
        }
        if (lane == 0) {
#pragma unroll
            for (int j = 0; j < 3; j++) {
                int e = ebase + 8 * j;
                int l = e - (e / Lc) * Lc;
                sev[warp][r * 3 + j] = (t >= lags[l]) ? acc[j] + sbias[e] : -INFINITY;
            }
        }
    }
    __syncwarp();

    // per-warp top-8 via rank counting (lanes 0..23, each ranks one slot)
    if (lane < 24) {
        float v = sev[warp][lane];
        int e = warp + 8 * (lane % 3) + 24 * (lane / 3);
        int rank = 0;
#pragma unroll
        for (int j = 0; j < 24; j++) {
            float vj = sev[warp][j];
            int ej = warp + 8 * (j % 3) + 24 * (j / 3);
            if (vj > v || (vj == v && ej < e)) rank++;
        }
        if (rank < 8) { scv[warp * 8 + rank] = v; scix[warp * 8 + rank] = e; }
    }
    __syncthreads();

    // merge 64 candidates -> global top-8 via rank counting
    if (tid < 64) {
        float v = scv[tid]; int e = scix[tid];
        int rank = 0;
#pragma unroll 8
        for (int j = 0; j < 64; j++) {
            float vj = scv[j]; int ej = scix[j];
            if (vj > v || (vj == v && ej < e)) rank++;
        }
        if (rank < KTOP) { swv[rank] = v; sidx[rank] = e; }
    }
    __syncthreads();

    // softmax over top-8, computed redundantly by every thread
    float w[KTOP];
    {
        float vs[KTOP]; float m = -INFINITY;
        bool allinf = (swv[0] == -INFINITY);   // top-1 is the max
#pragma unroll
        for (int r = 0; r < KTOP; r++) {
            float v = swv[r];
            vs[r] = (v == -INFINITY) ? -1e9f : v;
            m = fmaxf(m, vs[r]);
        }
        float z = 0.f;
#pragma unroll
        for (int r = 0; r < KTOP; r++) { w[r] = expf(vs[r] - m); z += w[r]; }
        float invz = allinf ? 0.f : 1.f / z;
#pragma unroll
        for (int r = 0; r < KTOP; r++) w[r] *= invz;
        if (tid == 0) wsum[bt] = allinf ? 0.f : 1.f;
    }

    // weighted delta sum: sum_k w_k * (peer[b,n_k,t,h] - peer[b,n_k,t-lag_k,h])
    float acc = 0.f;
#pragma unroll
    for (int r = 0; r < KTOP; r++) {
        float wr = w[r];
        if (wr != 0.f) {
            int e = sidx[r];
            int n = e / Lc, l = e - n * Lc;
            int lag = lags[l];
            const float* base = peer + (((size_t)b * Nc + n) * Tc + t) * Hc;
            acc += wr * (base[tid] - base[tid - lag * Hc]);
        }
    }
    dsum[(size_t)bt * Hc + tid] = acc;
}

// ---------------- layernorm, one block per row ----------------
__global__ void ln_kernel(const float* __restrict__ x, const float* __restrict__ g,
                          const float* __restrict__ bta, float* __restrict__ out)
{
    int row = blockIdx.x, tid = threadIdx.x;
    __shared__ float red1[8];
    __shared__ float red2[8];
    __shared__ float s_mu, s_var;

    float v = x[(size_t)row * Hc + tid];
    float s = v;
#pragma unroll
    for (int o = 16; o; o >>= 1) s += __shfl_xor_sync(0xffffffffu, s, o);
    if ((tid & 31) == 0) red1[tid >> 5] = s;
    __syncthreads();
    if (tid < 32) {
        float t2 = (tid < 8) ? red1[tid] : 0.f;
#pragma unroll
        for (int o = 4; o; o >>= 1) t2 += __shfl_xor_sync(0xffffffffu, t2, o);
        if (tid == 0) s_mu = t2 * (1.f / Hc);
    }
    __syncthreads();
    float mu = s_mu;
    float d = v - mu;
    float s2 = d * d;
#pragma unroll
    for (int o = 16; o; o >>= 1) s2 += __shfl_xor_sync(0xffffffffu, s2, o);
    if ((tid & 31) == 0) red2[tid >> 5] = s2;
    __syncthreads();
    if (tid < 32) {
        float t2 = (tid < 8) ? red2[tid] : 0.f;
#pragma unroll
        for (int o = 4; o; o >>= 1) t2 += __shfl_xor_sync(0xffffffffu, t2, o);
        if (tid == 0) s_var = t2 * (1.f / Hc);
    }
    __syncthreads();
    out[(size_t)row * Hc + tid] = d * rsqrtf(s_var + 1e-5f) * g[tid] + bta[tid];
}

// ---------------- launch ----------------
extern "C" void kernel_launch(void* const* d_in, const int* in_sizes, int n_in,
                              void* d_out, int out_size)
{
    const float* target_h = (const float*)d_in[0];
    const float* peer_h   = (const float*)d_in[1];
    const float* wq_w = (const float*)d_in[2];
    const float* wq_b = (const float*)d_in[3];
    const float* wk_w = (const float*)d_in[4];
    // d_in[5] = wk_b: uniform logit shift, output-invariant -> unused
    const float* wv_w = (const float*)d_in[6];
    const float* wv_b = (const float*)d_in[7];
    const float* f1_w = (const float*)d_in[8];
    const float* f1_b = (const float*)d_in[9];
    const float* f2_w = (const float*)d_in[10];
    const float* f2_b = (const float*)d_in[11];
    const float* ln_g = (const float*)d_in[12];
    const float* ln_b = (const float*)d_in[13];
    const float* alpha = (const float*)d_in[14];
    const float* lrs   = (const float*)d_in[15];
    const void* peer_mask = (const void*)d_in[16];
    const void* rmask     = (const void*)d_in[17];
    const int* target_id = (const int*)d_in[18];
    const int* peer_id   = (const int*)d_in[19];
    float* out = (float*)d_out;

    float *pA, *pc, *pQk, *pdsum, *pwsum, *plly, *ph1, *px, *pbias;
    cudaGetSymbolAddress((void**)&pA,    g_A);
    cudaGetSymbolAddress((void**)&pc,    g_c);
    cudaGetSymbolAddress((void**)&pQk,   g_Qk);
    cudaGetSymbolAddress((void**)&pdsum, g_dsum);
    cudaGetSymbolAddress((void**)&pwsum, g_wsum);
    cudaGetSymbolAddress((void**)&plly,  g_lly);
    cudaGetSymbolAddress((void**)&ph1,   g_h1);
    cudaGetSymbolAddress((void**)&px,    g_x);
    cudaGetSymbolAddress((void**)&pbias, g_bias);

    const float s = 0.0625f; // 1/sqrt(256)

    // 1: mask dtype detect + bias table
    detprep_kernel<<<1, 256>>>(lrs, peer_mask, rmask, target_id, peer_id, alpha, pbias);

    // 2: A = s * wq_w^T @ wk_w ; fused c = s * wq_b @ wk_w
    gemm32<true, false, false, false, false, false, true>
        <<<dim3(Hc / 32, Hc / 32), 128>>>(wq_w, wk_w, nullptr, nullptr, nullptr, pA,
                                          wq_b, pc, Hc, Hc, Hc, s);

    // 3: Qk = X @ A + c
    gemm32<false, false, false, true, false, false, false>
        <<<dim3(Hc / 32, BT / 32), 128>>>(target_h, pA, pc, nullptr, nullptr, pQk,
                                          nullptr, nullptr, BT, Hc, Hc, 1.f);

    // 4: logits + top-8 + weighted delta sum  (ncu profile slot)
    logits_kernel<<<BT, 256>>>(peer_h, pbias, pQk, pdsum, pwsum);

    // 5: ll_y = dsum @ wv_w^T + wsum*wv_b
    gemm32<false, true, false, true, true, false, false>
        <<<dim3(Hc / 32, BT / 32), 128>>>(pdsum, wv_w, wv_b, pwsum, nullptr, plly,
                                          nullptr, nullptr, BT, Hc, Hc, 1.f);

    // 6: h1 = elu(ll_y @ f1_w^T + f1_b)
    gemm32<false, true, true, true, false, false, false>
        <<<dim3(Hc / 32, BT / 32), 128>>>(plly, f1_w, f1_b, nullptr, nullptr, ph1,
                                          nullptr, nullptr, BT, Hc, Hc, 1.f);

    // 7: x = ll_y + h1 @ f2_w^T + f2_b
    gemm32<false, true, false, true, false, true, false>
        <<<dim3(Hc / 32, BT / 32), 128>>>(ph1, f2_w, f2_b, nullptr, plly, px,
                                          nullptr, nullptr, BT, Hc, Hc, 1.f);

    // 8: out = LN(x) * g + b
    ln_kernel<<<BT, Hc>>>(px, ln_g, ln_b, out);
}

// round 11
// speedup vs baseline: 1.0052x; 1.0052x over previous
#include <cuda_runtime.h>
#include <math.h>
#include <stdint.h>

#define Bc 4
#define Nc 64
#define Tc 384
#define Hc 256
#define Lc 3
#define NUc 500
#define KTOP 8
#define BT (Bc*Tc)   // 1536
#define NL (Nc*Lc)   // 192

// ---------------- scratch (device globals; no allocation allowed) ----------------
__device__ __align__(16) float g_A   [Hc*Hc];
__device__ __align__(16) float g_c   [Hc];
__device__ __align__(16) float g_Qk  [BT*Hc];
__device__ __align__(16) float g_dsum[BT*Hc];
__device__             float g_wsum[BT];
__device__ __align__(16) float g_lly [BT*Hc];
__device__ __align__(16) float g_h1  [BT*Hc];
__device__ __align__(16) float g_x   [BT*Hc];
__device__ __align__(16) float g_bias[Bc*NL];

__device__ __forceinline__ bool mask_read(const void* m, size_t i, int is_byte)
{
    if (is_byte) return ((const unsigned char*)m)[i] != 0;
    return ((const unsigned int*)m)[i] != 0u;   // int32 AND float32 (bit-pattern nonzero)
}

// ---------------- detprep: mask dtype detect + per-(b,e) bias table --------------
__global__ void detprep_kernel(const float* __restrict__ lrs,
                               const void* __restrict__ pm, const void* __restrict__ rm,
                               const int* __restrict__ target_id,
                               const int* __restrict__ peer_id,
                               const float* __restrict__ alpha_p,
                               float* __restrict__ biasTab)
{
    __shared__ unsigned s_g, s_o;
    if (threadIdx.x == 0) { s_g = 0u; s_o = 0u; }
    __syncthreads();
    const uint4* rm16 = (const uint4*)rm;
    const int n16 = 16384;  // scan first 256 KB of rank mask
    unsigned gt1 = 0u, off = 0u;
    for (int i = threadIdx.x; i < n16; i += blockDim.x) {
        uint4 v = rm16[i];
        unsigned w = v.x | v.y | v.z | v.w;
        gt1 |= w & 0xFEFEFEFEu;   // any byte value > 1 -> float32 words
        off |= w & 0xFFFFFF00u;   // nonzero byte at idx%4 != 0 -> uint8
    }
#pragma unroll
    for (int s = 16; s; s >>= 1) {
        gt1 |= __shfl_xor_sync(0xffffffffu, gt1, s);
        off |= __shfl_xor_sync(0xffffffffu, off, s);
    }
    if ((threadIdx.x & 31) == 0) {
        if (gt1) atomicOr(&s_g, 1u);
        if (off) atomicOr(&s_o, 1u);
    }
    __syncthreads();
    int ib = (s_g == 0u && s_o != 0u) ? 1 : 0;

    float alpha = *alpha_p;
    for (int idx = threadIdx.x; idx < Bc * NL; idx += blockDim.x) {
        int b = idx / NL, e = idx - b * NL;
        int n = e / Lc, l = e - n * Lc;
        int tgt = target_id[b], pid = peer_id[b * Nc + n];
        size_t offr = ((size_t)l * NUc + pid) * NUc + tgt;
        bool valid = mask_read(pm, b * Nc + n, ib) && mask_read(rm, offr, ib);
        biasTab[idx] = valid ? alpha * lrs[offr] : -INFINITY;
    }
}

// ---------------- 32x32x16 fp32 GEMM, 128 threads, 2x4/thread, double-buffered ---
// C[M,N] = scale * op(A)[M,K] @ op(B)[K,N] (+bias[n]*rowscale[m]) (+add[m,n]) (ELU)
// CVEC (A-gemm only): blockIdx.y==0 blocks emit cvec_out[n] = scale * sum_k cvec_in[k]*B[k][n]
template<bool A_T, bool B_T, bool DO_ELU, bool HAS_BIAS, bool HAS_SCALE, bool HAS_ADD, bool CVEC>
__global__ void gemm32(const float* __restrict__ A, const float* __restrict__ Bm,
                       const float* __restrict__ bias, const float* __restrict__ rowscale,
                       const float* __restrict__ addm, float* __restrict__ C,
                       const float* __restrict__ cvec_in, float* __restrict__ cvec_out,
                       int M, int N, int K, float scale)
{
    const int BK = 16;
    __shared__ __align__(16) float As[2][BK][36];
    __shared__ __align__(16) float Bs[2][BK][36];

    int tid = threadIdx.x;                 // 128 threads
    int m0 = blockIdx.y * 32, n0 = blockIdx.x * 32;
    int tx = tid & 7, ty = tid >> 3;       // tx 0..7 (cols of 4), ty 0..15 (rows of 2)

    // load indices (1 float4 per thread per tile)
    int aI0, aI1, bI0, bI1;
    if (!A_T) { aI0 = tid >> 2; aI1 = (tid & 3) << 2; }   // ar(0..31), ac{0,4,8,12}
    else      { aI0 = tid >> 3; aI1 = (tid & 7) << 2; }   // kr(0..15), mc(0..28)
    if (!B_T) { bI0 = tid >> 3; bI1 = (tid & 7) << 2; }   // kr(0..15), nc(0..28)
    else      { bI0 = tid >> 2; bI1 = (tid & 3) << 2; }   // nr(0..31), kc{0,4,8,12}

    float acc[2][4];
#pragma unroll
    for (int i = 0; i < 2; i++)
#pragma unroll
        for (int j = 0; j < 4; j++) acc[i][j] = 0.f;

    float cacc[4] = {0.f, 0.f, 0.f, 0.f};
    const bool do_cvec = CVEC && (blockIdx.y == 0) && (ty == 0);

    float4 va, vb;
    if (!A_T) va = *(const float4*)&A[(size_t)(m0 + aI0) * K + aI1];
    else      va = *(const float4*)&A[(size_t)aI0 * M + m0 + aI1];
    if (!B_T) vb = *(const float4*)&Bm[(size_t)bI0 * N + n0 + bI1];
    else      vb = *(const float4*)&Bm[(size_t)(n0 + bI0) * K + bI1];
    if (!A_T) { As[0][aI1+0][aI0]=va.x; As[0][aI1+1][aI0]=va.y; As[0][aI1+2][aI0]=va.z; As[0][aI1+3][aI0]=va.w; }
    else      { *(float4*)&As[0][aI0][aI1] = va; }
    if (!B_T) { *(float4*)&Bs[0][bI0][bI1] = vb; }
    else      { Bs[0][bI1+0][bI0]=vb.x; Bs[0][bI1+1][bI0]=vb.y; Bs[0][bI1+2][bI0]=vb.z; Bs[0][bI1+3][bI0]=vb.w; }
    __syncthreads();

    int buf = 0;
    for (int k0 = 0; k0 < K; k0 += BK) {
        bool has_next = (k0 + BK < K);
        if (has_next) {
            int kn = k0 + BK;
            if (!A_T) va = *(const float4*)&A[(size_t)(m0 + aI0) * K + kn + aI1];
            else      va = *(const float4*)&A[(size_t)(kn + aI0) * M + m0 + aI1];
            if (!B_T) vb = *(const float4*)&Bm[(size_t)(kn + bI0) * N + n0 + bI1];
            else      vb = *(const float4*)&Bm[(size_t)(n0 + bI0) * K + kn + bI1];
        }
#pragma unroll
        for (int kk = 0; kk < BK; kk++) {
            float2 a2 = *(const float2*)&As[buf][kk][ty << 1];
            float4 b4 = *(const float4*)&Bs[buf][kk][tx << 2];
            acc[0][0] += a2.x * b4.x; acc[0][1] += a2.x * b4.y;
            acc[0][2] += a2.x * b4.z; acc[0][3] += a2.x * b4.w;
            acc[1][0] += a2.y * b4.x; acc[1][1] += a2.y * b4.y;
            acc[1][2] += a2.y * b4.z; acc[1][3] += a2.y * b4.w;
            if (CVEC) {
                if (do_cvec) {
                    float wb = __ldg(&cvec_in[k0 + kk]);
                    cacc[0] += wb * b4.x; cacc[1] += wb * b4.y;
                    cacc[2] += wb * b4.z; cacc[3] += wb * b4.w;
                }
            }
        }
        if (has_next) {
            int s = buf ^ 1;
            if (!A_T) { As[s][aI1+0][aI0]=va.x; As[s][aI1+1][aI0]=va.y; As[s][aI1+2][aI0]=va.z; As[s][aI1+3][aI0]=va.w; }
            else      { *(float4*)&As[s][aI0][aI1] = va; }
            if (!B_T) { *(float4*)&Bs[s][bI0][bI1] = vb; }
            else      { Bs[s][bI1+0][bI0]=vb.x; Bs[s][bI1+1][bI0]=vb.y; Bs[s][bI1+2][bI0]=vb.z; Bs[s][bI1+3][bI0]=vb.w; }
        }
        __syncthreads();
        buf ^= 1;
    }

    if (CVEC) {
        if (do_cvec) {
            float4 cv = make_float4(cacc[0]*scale, cacc[1]*scale, cacc[2]*scale, cacc[3]*scale);
            *(float4*)&cvec_out[n0 + (tx << 2)] = cv;
        }
    }

#pragma unroll
    for (int i = 0; i < 2; i++) {
        int m = m0 + (ty << 1) + i;
        float rs = 1.f;
        if (HAS_SCALE) rs = rowscale[m];
        float4 outv;
        float* po = (float*)&outv;
#pragma unroll
        for (int j = 0; j < 4; j++) {
            int n = n0 + (tx << 2) + j;
            float v = acc[i][j] * scale;
            if (HAS_BIAS) v += bias[n] * rs;
            if (HAS_ADD)  v += addm[(size_t)m * N + n];
            if (DO_ELU)   v = (v > 0.f) ? v : expm1f(v);
            po[j] = v;
        }
        *(float4*)&C[(size_t)m * N + n0 + (tx << 2)] = outv;
    }
}

// ---------------- logits + parallel rank top-8 + weighted delta-sum --------------
__global__ void logits_kernel(const float* __restrict__ peer,
                              const float* __restrict__ biasTab,
                              const float* __restrict__ Qk,
                              float* __restrict__ dsum,
                              float* __restrict__ wsum)
{
    int bt = blockIdx.x;
    int b = bt / Tc, t = bt - b * Tc;
    int tid = threadIdx.x, lane = tid & 31, warp = tid >> 5;

    __shared__ __align__(16) float sQk[Hc];
    __shared__ float sbias[NL];
    __shared__ float sev[8][24];     // per-warp e-values
    __shared__ float scv[64];        // 8 warps x top-8 candidate values
    __shared__ int   scix[64];       // candidate flat-e indices
    __shared__ float swv[KTOP];      // global top-8 raw values
    __shared__ int   sidx[KTOP];

    if (tid < 64) ((float4*)sQk)[tid] = ((const float4*)(Qk + (size_t)bt * Hc))[tid];
    if (tid < NL) sbias[tid] = biasTab[b * NL + tid];
    __syncthreads();

    float4 q0 = ((const float4*)sQk)[lane];
    float4 q1 = ((const float4*)sQk)[lane + 32];
    const int lags[3] = {1, 5, 21};

    // dot phase: warp w handles e = w + 8j + 24r, j in 0..2, r in 0..7
#pragma unroll 1
    for (int r = 0; r < 8; r++) {
        int ebase = warp + 24 * r;
        float4 v0[3], v1[3];
        float acc[3];
#pragma unroll
        for (int j = 0; j < 3; j++) {
            int e = ebase + 8 * j;
            int n = e / Lc, l = e - n * Lc;
            int tr = t - lags[l]; if (tr < 0) tr = 0;
            const float4* row = (const float4*)(peer + (((size_t)b * Nc + n) * Tc + tr) * Hc);
            v0[j] = row[lane];
            v1[j] = row[lane + 32];
        }
#pragma unroll
        for (int j = 0; j < 3; j++) {
            acc[j] = v0[j].x*q0.x + v0[j].y*q0.y + v0[j].z*q0.z + v0[j].w*q0.w
                   + v1[j].x*q1.x + v1[j].y*q1.y + v1[j].z*q1.z + v1[j].w*q1.w;
        }
#pragma unroll
        for (int s = 16; s; s >>= 1) {
            acc[0] += __shfl_xor_sync(0xffffffffu, acc[0], s);
            acc[1] += __shfl_xor_sync(0xffffffffu, acc[1], s);
            acc[2] += __shfl_xor_sync(0xffffffffu, acc[2], s);
        }
        if (lane == 0) {
#pragma unroll
            for (int j = 0; j < 3; j++) {
                int e = ebase + 8 * j;
                int l = e - (e / Lc) * Lc;
                sev[warp][r * 3 + j] = (t >= lags[l]) ? acc[j] + sbias[e] : -INFINITY;
            }
        }
    }
    __syncwarp();

    // per-warp top-8 via rank counting (lanes 0..23, each ranks one slot)
    if (lane < 24) {
        float v = sev[warp][lane];
        int e = warp + 8 * (lane % 3) + 24 * (lane / 3);
        int rank = 0;
#pragma unroll
        for (int j = 0; j < 24; j++) {
            float vj = sev[warp][j];
            int ej = warp + 8 * (j % 3) + 24 * (j / 3);
            if (vj > v || (vj == v && ej < e)) rank++;
        }
        if (rank < 8) { scv[warp * 8 + rank] = v; scix[warp * 8 + rank] = e; }
    }
    __syncthreads();

    // merge 64 candidates -> global top-8 via rank counting
    if (tid < 64) {
        float v = scv[tid]; int e = scix[tid];
        int rank = 0;
#pragma unroll 8
        for (int j = 0; j < 64; j++) {
            float vj = scv[j]; int ej = scix[j];
            if (vj > v || (vj == v && ej < e)) rank++;
        }
        if (rank < KTOP) { swv[rank] = v; sidx[rank] = e; }
    }
    __syncthreads();

    // softmax over top-8, computed redundantly by every thread
    float w[KTOP];
    {
        float vs[KTOP]; float m = -INFINITY;
        bool allinf = (swv[0] == -INFINITY);   // top-1 is the max
#pragma unroll
        for (int r = 0; r < KTOP; r++) {
            float v = swv[r];
            vs[r] = (v == -INFINITY) ? -1e9f : v;
            m = fmaxf(m, vs[r]);
        }
        float z = 0.f;
#pragma unroll
        for (int r = 0; r < KTOP; r++) { w[r] = expf(vs[r] - m); z += w[r]; }
        float invz = allinf ? 0.f : 1.f / z;
#pragma unroll
        for (int r = 0; r < KTOP; r++) w[r] *= invz;
        if (tid == 0) wsum[bt] = allinf ? 0.f : 1.f;
    }

    // weighted delta sum: sum_k w_k * (peer[b,n_k,t,h] - peer[b,n_k,t-lag_k,h])
    float acc = 0.f;
#pragma unroll
    for (int r = 0; r < KTOP; r++) {
        float wr = w[r];
        if (wr != 0.f) {
            int e = sidx[r];
            int n = e / Lc, l = e - n * Lc;
            int lag = lags[l];
            const float* base = peer + (((size_t)b * Nc + n) * Tc + t) * Hc;
            acc += wr * (base[tid] - base[tid - lag * Hc]);
        }
    }
    dsum[(size_t)bt * Hc + tid] = acc;
}

// ---------------- layernorm, one block per row ----------------
__global__ void ln_kernel(const float* __restrict__ x, const float* __restrict__ g,
                          const float* __restrict__ bta, float* __restrict__ out)
{
    int row = blockIdx.x, tid = threadIdx.x;
    __shared__ float red1[8];
    __shared__ float red2[8];
    __shared__ float s_mu, s_var;

    float v = x[(size_t)row * Hc + tid];
    float s = v;
#pragma unroll
    for (int o = 16; o; o >>= 1) s += __shfl_xor_sync(0xffffffffu, s, o);
    if ((tid & 31) == 0) red1[tid >> 5] = s;
    __syncthreads();
    if (tid < 32) {
        float t2 = (tid < 8) ? red1[tid] : 0.f;
#pragma unroll
        for (int o = 4; o; o >>= 1) t2 += __shfl_xor_sync(0xffffffffu, t2, o);
        if (tid == 0) s_mu = t2 * (1.f / Hc);
    }
    __syncthreads();
    float mu = s_mu;
    float d = v - mu;
    float s2 = d * d;
#pragma unroll
    for (int o = 16; o; o >>= 1) s2 += __shfl_xor_sync(0xffffffffu, s2, o);
    if ((tid & 31) == 0) red2[tid >> 5] = s2;
    __syncthreads();
    if (tid < 32) {
        float t2 = (tid < 8) ? red2[tid] : 0.f;
#pragma unroll
        for (int o = 4; o; o >>= 1) t2 += __shfl_xor_sync(0xffffffffu, t2, o);
        if (tid == 0) s_var = t2 * (1.f / Hc);
    }
    __syncthreads();
    out[(size_t)row * Hc + tid] = d * rsqrtf(s_var + 1e-5f) * g[tid] + bta[tid];
}

// ---------------- launch ----------------
extern "C" void kernel_launch(void* const* d_in, const int* in_sizes, int n_in,
                              void* d_out, int out_size)
{
    const float* target_h = (const float*)d_in[0];
    const float* peer_h   = (const float*)d_in[1];
    const float* wq_w = (const float*)d_in[2];
    const float* wq_b = (const float*)d_in[3];
    const float* wk_w = (const float*)d_in[4];
    // d_in[5] = wk_b: uniform logit shift, output-invariant -> unused
    const float* wv_w = (const float*)d_in[6];
    const float* wv_b = (const float*)d_in[7];
    const float* f1_w = (const float*)d_in[8];
    const float* f1_b = (const float*)d_in[9];
    const float* f2_w = (const float*)d_in[10];
    const float* f2_b = (const float*)d_in[11];
    const float* ln_g = (const float*)d_in[12];
    const float* ln_b = (const float*)d_in[13];
    const float* alpha = (const float*)d_in[14];
    const float* lrs   = (const float*)d_in[15];
    const void* peer_mask = (const void*)d_in[16];
    const void* rmask     = (const void*)d_in[17];
    const int* target_id = (const int*)d_in[18];
    const int* peer_id   = (const int*)d_in[19];
    float* out = (float*)d_out;

    float *pA, *pc, *pQk, *pdsum, *pwsum, *plly, *ph1, *px, *pbias;
    cudaGetSymbolAddress((void**)&pA,    g_A);
    cudaGetSymbolAddress((void**)&pc,    g_c);
    cudaGetSymbolAddress((void**)&pQk,   g_Qk);
    cudaGetSymbolAddress((void**)&pdsum, g_dsum);
    cudaGetSymbolAddress((void**)&pwsum, g_wsum);
    cudaGetSymbolAddress((void**)&plly,  g_lly);
    cudaGetSymbolAddress((void**)&ph1,   g_h1);
    cudaGetSymbolAddress((void**)&px,    g_x);
    cudaGetSymbolAddress((void**)&pbias, g_bias);

    const float s = 0.0625f; // 1/sqrt(256)

    // 1: mask dtype detect + bias table
    detprep_kernel<<<1, 256>>>(lrs, peer_mask, rmask, target_id, peer_id, alpha, pbias);

    // 2: A = s * wq_w^T @ wk_w ; fused c = s * wq_b @ wk_w
    gemm32<true, false, false, false, false, false, true>
        <<<dim3(Hc / 32, Hc / 32), 128>>>(wq_w, wk_w, nullptr, nullptr, nullptr, pA,
                                          wq_b, pc, Hc, Hc, Hc, s);

    // 3: Qk = X @ A + c
    gemm32<false, false, false, true, false, false, false>
        <<<dim3(Hc / 32, BT / 32), 128>>>(target_h, pA, pc, nullptr, nullptr, pQk,
                                          nullptr, nullptr, BT, Hc, Hc, 1.f);

    // 4: logits + top-8 + weighted delta sum  (ncu profile slot)
    logits_kernel<<<BT, 256>>>(peer_h, pbias, pQk, pdsum, pwsum);

    // 5: ll_y = dsum @ wv_w^T + wsum*wv_b
    gemm32<false, true, false, true, true, false, false>
        <<<dim3(Hc / 32, BT / 32), 128>>>(pdsum, wv_w, wv_b, pwsum, nullptr, plly,
                                          nullptr, nullptr, BT, Hc, Hc, 1.f);

    // 6: h1 = elu(ll_y @ f1_w^T + f1_b)
    gemm32<false, true, true, true, false, false, false>
        <<<dim3(Hc / 32, BT / 32), 128>>>(plly, f1_w, f1_b, nullptr, nullptr, ph1,
                                          nullptr, nullptr, BT, Hc, Hc, 1.f);

    // 7: x = ll_y + h1 @ f2_w^T + f2_b
    gemm32<false, true, false, true, false, true, false>
        <<<dim3(Hc / 32, BT / 32), 128>>>(ph1, f2_w, f2_b, nullptr, plly, px,
                                          nullptr, nullptr, BT, Hc, Hc, 1.f);

    // 8: out = LN(x) * g + b
    ln_kernel<<<BT, Hc>>>(px, ln_g, ln_b, out);
}

// round 12
// speedup vs baseline: 1.1346x; 1.1287x over previous
#include <cuda_runtime.h>
#include <math.h>
#include <stdint.h>

#define Bc 4
#define Nc 64
#define Tc 384
#define Hc 256
#define Lc 3
#define NUc 500
#define KTOP 8
#define BT (Bc*Tc)   // 1536
#define NL (Nc*Lc)   // 192

// ---------------- scratch (device globals; no allocation allowed) ----------------
__device__ __align__(16) float g_A   [Hc*Hc];
__device__ __align__(16) float g_c   [Hc];
__device__ __align__(16) float g_Qk  [BT*Hc];
__device__ __align__(16) float g_dsum[BT*Hc];
__device__             float g_wsum[BT];
__device__ __align__(16) float g_lly [BT*Hc];
__device__ __align__(16) float g_h1  [BT*Hc];
__device__ __align__(16) float g_x   [BT*Hc];
__device__ __align__(16) float g_bias[Bc*NL];

__device__ __forceinline__ bool mask_read(const void* m, size_t i, int is_byte)
{
    if (is_byte) return ((const unsigned char*)m)[i] != 0;
    return ((const unsigned int*)m)[i] != 0u;   // int32 AND float32 (bit-pattern nonzero)
}

// ---------------- detprep (device fn, runs as aux block of gemmA) ----------------
__device__ void detprep_device(const float* __restrict__ lrs,
                               const void* __restrict__ pm, const void* __restrict__ rm,
                               const int* __restrict__ target_id,
                               const int* __restrict__ peer_id,
                               const float* __restrict__ alpha_p,
                               float* __restrict__ biasTab)
{
    __shared__ unsigned s_g, s_o;
    if (threadIdx.x == 0) { s_g = 0u; s_o = 0u; }
    __syncthreads();
    const uint4* rm16 = (const uint4*)rm;
    const int n16 = 16384;  // scan first 256 KB of rank mask
    unsigned gt1 = 0u, off = 0u;
    for (int i = threadIdx.x; i < n16; i += blockDim.x) {
        uint4 v = rm16[i];
        unsigned w = v.x | v.y | v.z | v.w;
        gt1 |= w & 0xFEFEFEFEu;   // any byte value > 1 -> float32 words
        off |= w & 0xFFFFFF00u;   // nonzero byte at idx%4 != 0 -> uint8
    }
#pragma unroll
    for (int s = 16; s; s >>= 1) {
        gt1 |= __shfl_xor_sync(0xffffffffu, gt1, s);
        off |= __shfl_xor_sync(0xffffffffu, off, s);
    }
    if ((threadIdx.x & 31) == 0) {
        if (gt1) atomicOr(&s_g, 1u);
        if (off) atomicOr(&s_o, 1u);
    }
    __syncthreads();
    int ib = (s_g == 0u && s_o != 0u) ? 1 : 0;

    float alpha = *alpha_p;
    for (int idx = threadIdx.x; idx < Bc * NL; idx += blockDim.x) {
        int b = idx / NL, e = idx - b * NL;
        int n = e / Lc, l = e - n * Lc;
        int tgt = target_id[b], pid = peer_id[b * Nc + n];
        size_t offr = ((size_t)l * NUc + pid) * NUc + tgt;
        bool valid = mask_read(pm, b * Nc + n, ib) && mask_read(rm, offr, ib);
        biasTab[idx] = valid ? alpha * lrs[offr] : -INFINITY;
    }
}

// ---------------- 32x64x16 fp32 GEMM, 128 threads, double-buffered smem ----------
// C[M,N] = scale * op(A)[M,K] @ op(B)[K,N] (+bias[n]*rowscale[m]) (+add[m,n]) (ELU)
// AUX (A-gemm only): blockIdx.y==0 blocks also emit cvec; the extra grid.y row runs detprep.
template<bool A_T, bool B_T, bool DO_ELU, bool HAS_BIAS, bool HAS_SCALE, bool HAS_ADD, bool AUX>
__global__ void gemm32(const float* __restrict__ A, const float* __restrict__ Bm,
                       const float* __restrict__ bias, const float* __restrict__ rowscale,
                       const float* __restrict__ addm, float* __restrict__ C,
                       const float* __restrict__ cvec_in, float* __restrict__ cvec_out,
                       int M, int N, int K, float scale,
                       const float* lrs, const void* pm, const void* rm,
                       const int* target_id, const int* peer_id,
                       const float* alpha_p, float* biasTab)
{
    if (AUX && blockIdx.y == gridDim.y - 1) {
        if (blockIdx.x == 0)
            detprep_device(lrs, pm, rm, target_id, peer_id, alpha_p, biasTab);
        return;
    }

    const int BM = 32, BN = 64, BK = 16;
    __shared__ __align__(16) float As[2][BK][BM + 4];
    __shared__ __align__(16) float Bs[2][BK][BN + 4];

    int tid = threadIdx.x;                 // 128 threads
    int m0 = blockIdx.y * BM, n0 = blockIdx.x * BN;
    int tx = tid & 15, ty = tid >> 4;      // ty in 0..7

    int aI0, aI1, bI0, bI1;
    if (!A_T) { aI0 = tid >> 2; aI1 = (tid & 3) << 2; }
    else      { aI0 = tid >> 3; aI1 = (tid & 7) << 2; }
    if (!B_T) { bI0 = tid >> 4; bI1 = (tid & 15) << 2; }
    else      { bI0 = tid >> 2; bI1 = (tid & 3) << 2; }

    float acc[4][4];
#pragma unroll
    for (int i = 0; i < 4; i++)
#pragma unroll
        for (int j = 0; j < 4; j++) acc[i][j] = 0.f;

    float cacc[4] = {0.f, 0.f, 0.f, 0.f};
    const bool do_cvec = AUX && (blockIdx.y == 0) && (ty == 0);

    float4 va, vb0, vb1;
    if (!A_T) va = *(const float4*)&A[(size_t)(m0 + aI0) * K + aI1];
    else      va = *(const float4*)&A[(size_t)aI0 * M + m0 + aI1];
    if (!B_T) { vb0 = *(const float4*)&Bm[(size_t)bI0 * N + n0 + bI1];
                vb1 = *(const float4*)&Bm[(size_t)(bI0 + 8) * N + n0 + bI1]; }
    else      { vb0 = *(const float4*)&Bm[(size_t)(n0 + bI0) * K + bI1];
                vb1 = *(const float4*)&Bm[(size_t)(n0 + bI0 + 32) * K + bI1]; }
    if (!A_T) { As[0][aI1+0][aI0]=va.x; As[0][aI1+1][aI0]=va.y; As[0][aI1+2][aI0]=va.z; As[0][aI1+3][aI0]=va.w; }
    else      { *(float4*)&As[0][aI0][aI1] = va; }
    if (!B_T) { *(float4*)&Bs[0][bI0][bI1] = vb0; *(float4*)&Bs[0][bI0+8][bI1] = vb1; }
    else      { Bs[0][bI1+0][bI0]=vb0.x; Bs[0][bI1+1][bI0]=vb0.y; Bs[0][bI1+2][bI0]=vb0.z; Bs[0][bI1+3][bI0]=vb0.w;
                Bs[0][bI1+0][bI0+32]=vb1.x; Bs[0][bI1+1][bI0+32]=vb1.y; Bs[0][bI1+2][bI0+32]=vb1.z; Bs[0][bI1+3][bI0+32]=vb1.w; }
    __syncthreads();

    int buf = 0;
    for (int k0 = 0; k0 < K; k0 += BK) {
        bool has_next = (k0 + BK < K);
        if (has_next) {
            int kn = k0 + BK;
            if (!A_T) va = *(const float4*)&A[(size_t)(m0 + aI0) * K + kn + aI1];
            else      va = *(const float4*)&A[(size_t)(kn + aI0) * M + m0 + aI1];
            if (!B_T) { vb0 = *(const float4*)&Bm[(size_t)(kn + bI0) * N + n0 + bI1];
                        vb1 = *(const float4*)&Bm[(size_t)(kn + bI0 + 8) * N + n0 + bI1]; }
            else      { vb0 = *(const float4*)&Bm[(size_t)(n0 + bI0) * K + kn + bI1];
                        vb1 = *(const float4*)&Bm[(size_t)(n0 + bI0 + 32) * K + kn + bI1]; }
        }
#pragma unroll
        for (int kk = 0; kk < BK; kk++) {
            float4 a4 = *(const float4*)&As[buf][kk][ty << 2];
            float4 b4 = *(const float4*)&Bs[buf][kk][tx << 2];
            float a[4] = {a4.x, a4.y, a4.z, a4.w};
            float b[4] = {b4.x, b4.y, b4.z, b4.w};
#pragma unroll
            for (int i = 0; i < 4; i++)
#pragma unroll
                for (int j = 0; j < 4; j++) acc[i][j] += a[i] * b[j];
            if (AUX) {
                if (do_cvec) {
                    float wb = __ldg(&cvec_in[k0 + kk]);
                    cacc[0] += wb * b4.x; cacc[1] += wb * b4.y;
                    cacc[2] += wb * b4.z; cacc[3] += wb * b4.w;
                }
            }
        }
        if (has_next) {
            int s = buf ^ 1;
            if (!A_T) { As[s][aI1+0][aI0]=va.x; As[s][aI1+1][aI0]=va.y; As[s][aI1+2][aI0]=va.z; As[s][aI1+3][aI0]=va.w; }
            else      { *(float4*)&As[s][aI0][aI1] = va; }
            if (!B_T) { *(float4*)&Bs[s][bI0][bI1] = vb0; *(float4*)&Bs[s][bI0+8][bI1] = vb1; }
            else      { Bs[s][bI1+0][bI0]=vb0.x; Bs[s][bI1+1][bI0]=vb0.y; Bs[s][bI1+2][bI0]=vb0.z; Bs[s][bI1+3][bI0]=vb0.w;
                        Bs[s][bI1+0][bI0+32]=vb1.x; Bs[s][bI1+1][bI0+32]=vb1.y; Bs[s][bI1+2][bI0+32]=vb1.z; Bs[s][bI1+3][bI0+32]=vb1.w; }
        }
        __syncthreads();
        buf ^= 1;
    }

    if (AUX) {
        if (do_cvec) {
            float4 cv = make_float4(cacc[0]*scale, cacc[1]*scale, cacc[2]*scale, cacc[3]*scale);
            *(float4*)&cvec_out[n0 + (tx << 2)] = cv;
        }
    }

#pragma unroll
    for (int i = 0; i < 4; i++) {
        int m = m0 + (ty << 2) + i;
        float rs = 1.f;
        if (HAS_SCALE) rs = rowscale[m];
        float4 outv;
        float* po = (float*)&outv;
#pragma unroll
        for (int j = 0; j < 4; j++) {
            int n = n0 + (tx << 2) + j;
            float v = acc[i][j] * scale;
            if (HAS_BIAS) v += bias[n] * rs;
            if (HAS_ADD)  v += addm[(size_t)m * N + n];
            if (DO_ELU)   v = (v > 0.f) ? v : expm1f(v);
            po[j] = v;
        }
        *(float4*)&C[(size_t)m * N + n0 + (tx << 2)] = outv;
    }
}

// ---------------- logits + parallel rank top-8 + weighted delta-sum --------------
// Per-(b,t)-invariant row offsets + time-folded bias precomputed into smem.
__global__ void logits_kernel(const float* __restrict__ peer,
                              const float* __restrict__ biasTab,
                              const float* __restrict__ Qk,
                              float* __restrict__ dsum,
                              float* __restrict__ wsum)
{
    int bt = blockIdx.x;
    int b = bt / Tc, t = bt - b * Tc;
    int tid = threadIdx.x, lane = tid & 31, warp = tid >> 5;

    __shared__ __align__(16) float sQk[Hc];
    __shared__ int   soff[NL];       // element offset of lagged row start
    __shared__ float sfb [NL];       // bias folded with time-validity
    __shared__ float sev[8][24];     // per-warp e-values
    __shared__ float scv[64];        // 8 warps x top-8 candidate values
    __shared__ int   scix[64];       // candidate flat-e indices
    __shared__ float swv[KTOP];      // global top-8 raw values
    __shared__ int   sidx[KTOP];

    if (tid < 64) ((float4*)sQk)[tid] = ((const float4*)(Qk + (size_t)bt * Hc))[tid];
    if (tid < NL) {
        int e = tid;
        int n = e / Lc, l = e - n * Lc;
        int lag = (l == 0) ? 1 : (l == 1) ? 5 : 21;
        int tr = t - lag;
        sfb[e] = (tr >= 0) ? biasTab[b * NL + e] : -INFINITY;
        if (tr < 0) tr = 0;
        soff[e] = ((b * Nc + n) * Tc + tr) << 8;   // * Hc
    }
    __syncthreads();

    float4 q0 = ((const float4*)sQk)[lane];
    float4 q1 = ((const float4*)sQk)[lane + 32];

    // dot phase: warp w handles e = w + 8j + 24r
#pragma unroll 1
    for (int r = 0; r < 8; r++) {
        int ebase = warp + 24 * r;
        float4 v0[3], v1[3];
        float acc[3];
#pragma unroll
        for (int j = 0; j < 3; j++) {
            const float4* row = (const float4*)(peer + (size_t)(unsigned)soff[ebase + 8 * j]);
            v0[j] = row[lane];
            v1[j] = row[lane + 32];
        }
#pragma unroll
        for (int j = 0; j < 3; j++) {
            acc[j] = v0[j].x*q0.x + v0[j].y*q0.y + v0[j].z*q0.z + v0[j].w*q0.w
                   + v1[j].x*q1.x + v1[j].y*q1.y + v1[j].z*q1.z + v1[j].w*q1.w;
        }
#pragma unroll
        for (int s = 16; s; s >>= 1) {
            acc[0] += __shfl_xor_sync(0xffffffffu, acc[0], s);
            acc[1] += __shfl_xor_sync(0xffffffffu, acc[1], s);
            acc[2] += __shfl_xor_sync(0xffffffffu, acc[2], s);
        }
        if (lane == 0) {
#pragma unroll
            for (int j = 0; j < 3; j++)
                sev[warp][r * 3 + j] = acc[j] + sfb[ebase + 8 * j];
        }
    }
    __syncwarp();

    // per-warp top-8 via rank counting (lanes 0..23, each ranks one slot)
    if (lane < 24) {
        float v = sev[warp][lane];
        int e = warp + 8 * (lane % 3) + 24 * (lane / 3);
        int rank = 0;
#pragma unroll
        for (int j = 0; j < 24; j++) {
            float vj = sev[warp][j];
            int ej = warp + 8 * (j % 3) + 24 * (j / 3);
            if (vj > v || (vj == v && ej < e)) rank++;
        }
        if (rank < 8) { scv[warp * 8 + rank] = v; scix[warp * 8 + rank] = e; }
    }
    __syncthreads();

    // merge 64 candidates -> global top-8 via rank counting
    if (tid < 64) {
        float v = scv[tid]; int e = scix[tid];
        int rank = 0;
#pragma unroll 8
        for (int j = 0; j < 64; j++) {
            float vj = scv[j]; int ej = scix[j];
            if (vj > v || (vj == v && ej < e)) rank++;
        }
        if (rank < KTOP) { swv[rank] = v; sidx[rank] = e; }
    }
    __syncthreads();

    // softmax over top-8, computed redundantly by every thread
    float w[KTOP];
    {
        float vs[KTOP]; float m = -INFINITY;
        bool allinf = (swv[0] == -INFINITY);   // top-1 is the max
#pragma unroll
        for (int r = 0; r < KTOP; r++) {
            float v = swv[r];
            vs[r] = (v == -INFINITY) ? -1e9f : v;
            m = fmaxf(m, vs[r]);
        }
        float z = 0.f;
#pragma unroll
        for (int r = 0; r < KTOP; r++) { w[r] = expf(vs[r] - m); z += w[r]; }
        float invz = allinf ? 0.f : 1.f / z;
#pragma unroll
        for (int r = 0; r < KTOP; r++) w[r] *= invz;
        if (tid == 0) wsum[bt] = allinf ? 0.f : 1.f;
    }

    // weighted delta sum: sum_k w_k * (peer[b,n_k,t,h] - peer[b,n_k,t-lag_k,h])
    const int lags[3] = {1, 5, 21};
    float acc = 0.f;
#pragma unroll
    for (int r = 0; r < KTOP; r++) {
        float wr = w[r];
        if (wr != 0.f) {
            int e = sidx[r];
            int n = e / Lc, l = e - n * Lc;
            int lag = lags[l];
            const float* base = peer + (((size_t)b * Nc + n) * Tc + t) * Hc;
            acc += wr * (base[tid] - base[tid - lag * Hc]);
        }
    }
    dsum[(size_t)bt * Hc + tid] = acc;
}

// ---------------- layernorm, one block per row ----------------
__global__ void ln_kernel(const float* __restrict__ x, const float* __restrict__ g,
                          const float* __restrict__ bta, float* __restrict__ out)
{
    int row = blockIdx.x, tid = threadIdx.x;
    __shared__ float red1[8];
    __shared__ float red2[8];
    __shared__ float s_mu, s_var;

    float v = x[(size_t)row * Hc + tid];
    float s = v;
#pragma unroll
    for (int o = 16; o; o >>= 1) s += __shfl_xor_sync(0xffffffffu, s, o);
    if ((tid & 31) == 0) red1[tid >> 5] = s;
    __syncthreads();
    if (tid < 32) {
        float t2 = (tid < 8) ? red1[tid] : 0.f;
#pragma unroll
        for (int o = 4; o; o >>= 1) t2 += __shfl_xor_sync(0xffffffffu, t2, o);
        if (tid == 0) s_mu = t2 * (1.f / Hc);
    }
    __syncthreads();
    float mu = s_mu;
    float d = v - mu;
    float s2 = d * d;
#pragma unroll
    for (int o = 16; o; o >>= 1) s2 += __shfl_xor_sync(0xffffffffu, s2, o);
    if ((tid & 31) == 0) red2[tid >> 5] = s2;
    __syncthreads();
    if (tid < 32) {
        float t2 = (tid < 8) ? red2[tid] : 0.f;
#pragma unroll
        for (int o = 4; o; o >>= 1) t2 += __shfl_xor_sync(0xffffffffu, t2, o);
        if (tid == 0) s_var = t2 * (1.f / Hc);
    }
    __syncthreads();
    out[(size_t)row * Hc + tid] = d * rsqrtf(s_var + 1e-5f) * g[tid] + bta[tid];
}

// ---------------- launch ----------------
extern "C" void kernel_launch(void* const* d_in, const int* in_sizes, int n_in,
                              void* d_out, int out_size)
{
    const float* target_h = (const float*)d_in[0];
    const float* peer_h   = (const float*)d_in[1];
    const float* wq_w = (const float*)d_in[2];
    const float* wq_b = (const float*)d_in[3];
    const float* wk_w = (const float*)d_in[4];
    // d_in[5] = wk_b: uniform logit shift, output-invariant -> unused
    const float* wv_w = (const float*)d_in[6];
    const float* wv_b = (const float*)d_in[7];
    const float* f1_w = (const float*)d_in[8];
    const float* f1_b = (const float*)d_in[9];
    const float* f2_w = (const float*)d_in[10];
    const float* f2_b = (const float*)d_in[11];
    const float* ln_g = (const float*)d_in[12];
    const float* ln_b = (const float*)d_in[13];
    const float* alpha = (const float*)d_in[14];
    const float* lrs   = (const float*)d_in[15];
    const void* peer_mask = (const void*)d_in[16];
    const void* rmask     = (const void*)d_in[17];
    const int* target_id = (const int*)d_in[18];
    const int* peer_id   = (const int*)d_in[19];
    float* out = (float*)d_out;

    float *pA, *pc, *pQk, *pdsum, *pwsum, *plly, *ph1, *px, *pbias;
    cudaGetSymbolAddress((void**)&pA,    g_A);
    cudaGetSymbolAddress((void**)&pc,    g_c);
    cudaGetSymbolAddress((void**)&pQk,   g_Qk);
    cudaGetSymbolAddress((void**)&pdsum, g_dsum);
    cudaGetSymbolAddress((void**)&pwsum, g_wsum);
    cudaGetSymbolAddress((void**)&plly,  g_lly);
    cudaGetSymbolAddress((void**)&ph1,   g_h1);
    cudaGetSymbolAddress((void**)&px,    g_x);
    cudaGetSymbolAddress((void**)&pbias, g_bias);

    const float s = 0.0625f; // 1/sqrt(256)

    // 1: A = s * wq_w^T @ wk_w ; fused c = s * wq_b @ wk_w ; aux row = detprep
    gemm32<true, false, false, false, false, false, true>
        <<<dim3(Hc / 64, Hc / 32 + 1), 128>>>(wq_w, wk_w, nullptr, nullptr, nullptr, pA,
                                              wq_b, pc, Hc, Hc, Hc, s,
                                              lrs, peer_mask, rmask, target_id, peer_id,
                                              alpha, pbias);

    // 2: Qk = X @ A + c
    gemm32<false, false, false, true, false, false, false>
        <<<dim3(Hc / 64, BT / 32), 128>>>(target_h, pA, pc, nullptr, nullptr, pQk,
                                          nullptr, nullptr, BT, Hc, Hc, 1.f,
                                          nullptr, nullptr, nullptr, nullptr, nullptr,
                                          nullptr, nullptr);

    // 3: logits + top-8 + weighted delta sum
    logits_kernel<<<BT, 256>>>(peer_h, pbias, pQk, pdsum, pwsum);

    // 4: ll_y = dsum @ wv_w^T + wsum*wv_b   (ncu profile slot)
    gemm32<false, true, false, true, true, false, false>
        <<<dim3(Hc / 64, BT / 32), 128>>>(pdsum, wv_w, wv_b, pwsum, nullptr, plly,
                                          nullptr, nullptr, BT, Hc, Hc, 1.f,
                                          nullptr, nullptr, nullptr, nullptr, nullptr,
                                          nullptr, nullptr);

    // 5: h1 = elu(ll_y @ f1_w^T + f1_b)
    gemm32<false, true, true, true, false, false, false>
        <<<dim3(Hc / 64, BT / 32), 128>>>(plly, f1_w, f1_b, nullptr, nullptr, ph1,
                                          nullptr, nullptr, BT, Hc, Hc, 1.f,
                                          nullptr, nullptr, nullptr, nullptr, nullptr,
                                          nullptr, nullptr);

    // 6: x = ll_y + h1 @ f2_w^T + f2_b
    gemm32<false, true, false, true, false, true, false>
        <<<dim3(Hc / 64, BT / 32), 128>>>(ph1, f2_w, f2_b, nullptr, plly, px,
                                          nullptr, nullptr, BT, Hc, Hc, 1.f,
                                          nullptr, nullptr, nullptr, nullptr, nullptr,
                                          nullptr, nullptr);

    // 7: out = LN(x) * g + b
    ln_kernel<<<BT, Hc>>>(px, ln_g, ln_b, out);
}

// round 13
// speedup vs baseline: 1.1370x; 1.0021x over previous
#include <cuda_runtime.h>
#include <math.h>
#include <stdint.h>

#define Bc 4
#define Nc 64
#define Tc 384
#define Hc 256
#define Lc 3
#define NUc 500
#define KTOP 8
#define BT (Bc*Tc)   // 1536
#define NL (Nc*Lc)   // 192

// ---------------- scratch (device globals; no allocation allowed) ----------------
__device__ __align__(16) float g_A   [Hc*Hc];
__device__ __align__(16) float g_c   [Hc];
__device__ __align__(16) float g_Qk  [BT*Hc];
__device__ __align__(16) float g_dsum[BT*Hc];
__device__             float g_wsum[BT];
__device__ __align__(16) float g_lly [BT*Hc];
__device__ __align__(16) float g_h1  [BT*Hc];
__device__ __align__(16) float g_x   [BT*Hc];
__device__ __align__(16) float g_bias[Bc*NL];

__device__ __forceinline__ bool mask_read(const void* m, size_t i, int is_byte)
{
    if (is_byte) return ((const unsigned char*)m)[i] != 0;
    return ((const unsigned int*)m)[i] != 0u;   // int32 AND float32 (bit-pattern nonzero)
}

// ---------------- detprep (device fn, runs as aux block of gemmA) ----------------
__device__ void detprep_device(const float* __restrict__ lrs,
                               const void* __restrict__ pm, const void* __restrict__ rm,
                               const int* __restrict__ target_id,
                               const int* __restrict__ peer_id,
                               const float* __restrict__ alpha_p,
                               float* __restrict__ biasTab)
{
    __shared__ unsigned s_g, s_o;
    if (threadIdx.x == 0) { s_g = 0u; s_o = 0u; }
    __syncthreads();
    const uint4* rm16 = (const uint4*)rm;
    const int n16 = 16384;  // scan first 256 KB of rank mask
    unsigned gt1 = 0u, off = 0u;
    for (int i = threadIdx.x; i < n16; i += blockDim.x) {
        uint4 v = rm16[i];
        unsigned w = v.x | v.y | v.z | v.w;
        gt1 |= w & 0xFEFEFEFEu;   // any byte value > 1 -> float32 words
        off |= w & 0xFFFFFF00u;   // nonzero byte at idx%4 != 0 -> uint8
    }
#pragma unroll
    for (int s = 16; s; s >>= 1) {
        gt1 |= __shfl_xor_sync(0xffffffffu, gt1, s);
        off |= __shfl_xor_sync(0xffffffffu, off, s);
    }
    if ((threadIdx.x & 31) == 0) {
        if (gt1) atomicOr(&s_g, 1u);
        if (off) atomicOr(&s_o, 1u);
    }
    __syncthreads();
    int ib = (s_g == 0u && s_o != 0u) ? 1 : 0;

    float alpha = *alpha_p;
    for (int idx = threadIdx.x; idx < Bc * NL; idx += blockDim.x) {
        int b = idx / NL, e = idx - b * NL;
        int n = e / Lc, l = e - n * Lc;
        int tgt = target_id[b], pid = peer_id[b * Nc + n];
        size_t offr = ((size_t)l * NUc + pid) * NUc + tgt;
        bool valid = mask_read(pm, b * Nc + n, ib) && mask_read(rm, offr, ib);
        biasTab[idx] = valid ? alpha * lrs[offr] : -INFINITY;
    }
}

// ---------------- 32x64x16 fp32 GEMM, 128 threads, double-buffered smem ----------
// C[M,N] = scale * op(A)[M,K] @ op(B)[K,N] (+bias[n]*rowscale[m]) (+add[m,n]) (ELU)
// AUX (A-gemm only): blockIdx.y==0 blocks also emit cvec; the extra grid.y row runs detprep.
template<bool A_T, bool B_T, bool DO_ELU, bool HAS_BIAS, bool HAS_SCALE, bool HAS_ADD, bool AUX>
__global__ void gemm32(const float* __restrict__ A, const float* __restrict__ Bm,
                       const float* __restrict__ bias, const float* __restrict__ rowscale,
                       const float* __restrict__ addm, float* __restrict__ C,
                       const float* __restrict__ cvec_in, float* __restrict__ cvec_out,
                       int M, int N, int K, float scale,
                       const float* lrs, const void* pm, const void* rm,
                       const int* target_id, const int* peer_id,
                       const float* alpha_p, float* biasTab)
{
    if (AUX && blockIdx.y == gridDim.y - 1) {
        if (blockIdx.x == 0)
            detprep_device(lrs, pm, rm, target_id, peer_id, alpha_p, biasTab);
        return;
    }

    const int BM = 32, BN = 64, BK = 16;
    __shared__ __align__(16) float As[2][BK][BM + 4];
    __shared__ __align__(16) float Bs[2][BK][BN + 4];

    int tid = threadIdx.x;                 // 128 threads
    int m0 = blockIdx.y * BM, n0 = blockIdx.x * BN;
    int tx = tid & 15, ty = tid >> 4;      // ty in 0..7

    int aI0, aI1, bI0, bI1;
    if (!A_T) { aI0 = tid >> 2; aI1 = (tid & 3) << 2; }
    else      { aI0 = tid >> 3; aI1 = (tid & 7) << 2; }
    if (!B_T) { bI0 = tid >> 4; bI1 = (tid & 15) << 2; }
    else      { bI0 = tid >> 2; bI1 = (tid & 3) << 2; }

    float acc[4][4];
#pragma unroll
    for (int i = 0; i < 4; i++)
#pragma unroll
        for (int j = 0; j < 4; j++) acc[i][j] = 0.f;

    float cacc[4] = {0.f, 0.f, 0.f, 0.f};
    const bool do_cvec = AUX && (blockIdx.y == 0) && (ty == 0);

    float4 va, vb0, vb1;
    if (!A_T) va = *(const float4*)&A[(size_t)(m0 + aI0) * K + aI1];
    else      va = *(const float4*)&A[(size_t)aI0 * M + m0 + aI1];
    if (!B_T) { vb0 = *(const float4*)&Bm[(size_t)bI0 * N + n0 + bI1];
                vb1 = *(const float4*)&Bm[(size_t)(bI0 + 8) * N + n0 + bI1]; }
    else      { vb0 = *(const float4*)&Bm[(size_t)(n0 + bI0) * K + bI1];
                vb1 = *(const float4*)&Bm[(size_t)(n0 + bI0 + 32) * K + bI1]; }
    if (!A_T) { As[0][aI1+0][aI0]=va.x; As[0][aI1+1][aI0]=va.y; As[0][aI1+2][aI0]=va.z; As[0][aI1+3][aI0]=va.w; }
    else      { *(float4*)&As[0][aI0][aI1] = va; }
    if (!B_T) { *(float4*)&Bs[0][bI0][bI1] = vb0; *(float4*)&Bs[0][bI0+8][bI1] = vb1; }
    else      { Bs[0][bI1+0][bI0]=vb0.x; Bs[0][bI1+1][bI0]=vb0.y; Bs[0][bI1+2][bI0]=vb0.z; Bs[0][bI1+3][bI0]=vb0.w;
                Bs[0][bI1+0][bI0+32]=vb1.x; Bs[0][bI1+1][bI0+32]=vb1.y; Bs[0][bI1+2][bI0+32]=vb1.z; Bs[0][bI1+3][bI0+32]=vb1.w; }
    __syncthreads();

    int buf = 0;
    for (int k0 = 0; k0 < K; k0 += BK) {
        bool has_next = (k0 + BK < K);
        if (has_next) {
            int kn = k0 + BK;
            if (!A_T) va = *(const float4*)&A[(size_t)(m0 + aI0) * K + kn + aI1];
            else      va = *(const float4*)&A[(size_t)(kn + aI0) * M + m0 + aI1];
            if (!B_T) { vb0 = *(const float4*)&Bm[(size_t)(kn + bI0) * N + n0 + bI1];
                        vb1 = *(const float4*)&Bm[(size_t)(kn + bI0 + 8) * N + n0 + bI1]; }
            else      { vb0 = *(const float4*)&Bm[(size_t)(n0 + bI0) * K + kn + bI1];
                        vb1 = *(const float4*)&Bm[(size_t)(n0 + bI0 + 32) * K + kn + bI1]; }
        }
#pragma unroll
        for (int kk = 0; kk < BK; kk++) {
            float4 a4 = *(const float4*)&As[buf][kk][ty << 2];
            float4 b4 = *(const float4*)&Bs[buf][kk][tx << 2];
            float a[4] = {a4.x, a4.y, a4.z, a4.w};
            float b[4] = {b4.x, b4.y, b4.z, b4.w};
#pragma unroll
            for (int i = 0; i < 4; i++)
#pragma unroll
                for (int j = 0; j < 4; j++) acc[i][j] += a[i] * b[j];
            if (AUX) {
                if (do_cvec) {
                    float wb = __ldg(&cvec_in[k0 + kk]);
                    cacc[0] += wb * b4.x; cacc[1] += wb * b4.y;
                    cacc[2] += wb * b4.z; cacc[3] += wb * b4.w;
                }
            }
        }
        if (has_next) {
            int s = buf ^ 1;
            if (!A_T) { As[s][aI1+0][aI0]=va.x; As[s][aI1+1][aI0]=va.y; As[s][aI1+2][aI0]=va.z; As[s][aI1+3][aI0]=va.w; }
            else      { *(float4*)&As[s][aI0][aI1] = va; }
            if (!B_T) { *(float4*)&Bs[s][bI0][bI1] = vb0; *(float4*)&Bs[s][bI0+8][bI1] = vb1; }
            else      { Bs[s][bI1+0][bI0]=vb0.x; Bs[s][bI1+1][bI0]=vb0.y; Bs[s][bI1+2][bI0]=vb0.z; Bs[s][bI1+3][bI0]=vb0.w;
                        Bs[s][bI1+0][bI0+32]=vb1.x; Bs[s][bI1+1][bI0+32]=vb1.y; Bs[s][bI1+2][bI0+32]=vb1.z; Bs[s][bI1+3][bI0+32]=vb1.w; }
        }
        __syncthreads();
        buf ^= 1;
    }

    if (AUX) {
        if (do_cvec) {
            float4 cv = make_float4(cacc[0]*scale, cacc[1]*scale, cacc[2]*scale, cacc[3]*scale);
            *(float4*)&cvec_out[n0 + (tx << 2)] = cv;
        }
    }

#pragma unroll
    for (int i = 0; i < 4; i++) {
        int m = m0 + (ty << 2) + i;
        float rs = 1.f;
        if (HAS_SCALE) rs = rowscale[m];
        float4 outv;
        float* po = (float*)&outv;
#pragma unroll
        for (int j = 0; j < 4; j++) {
            int n = n0 + (tx << 2) + j;
            float v = acc[i][j] * scale;
            if (HAS_BIAS) v += bias[n] * rs;
            if (HAS_ADD)  v += addm[(size_t)m * N + n];
            if (DO_ELU)   v = (v > 0.f) ? v : expm1f(v);
            po[j] = v;
        }
        *(float4*)&C[(size_t)m * N + n0 + (tx << 2)] = outv;
    }
}

// ---------------- logits + parallel rank top-8 + weighted delta-sum --------------
// Per-(b,t)-invariant row offsets + time-folded bias precomputed into smem.
__global__ void logits_kernel(const float* __restrict__ peer,
                              const float* __restrict__ biasTab,
                              const float* __restrict__ Qk,
                              float* __restrict__ dsum,
                              float* __restrict__ wsum)
{
    int bt = blockIdx.x;
    int b = bt / Tc, t = bt - b * Tc;
    int tid = threadIdx.x, lane = tid & 31, warp = tid >> 5;

    __shared__ __align__(16) float sQk[Hc];
    __shared__ int   soff[NL];       // element offset of lagged row start
    __shared__ float sfb [NL];       // bias folded with time-validity
    __shared__ float sev[8][24];     // per-warp e-values
    __shared__ float scv[64];        // 8 warps x top-8 candidate values
    __shared__ int   scix[64];       // candidate flat-e indices
    __shared__ float swv[KTOP];      // global top-8 raw values
    __shared__ int   sidx[KTOP];

    if (tid < 64) ((float4*)sQk)[tid] = ((const float4*)(Qk + (size_t)bt * Hc))[tid];
    if (tid < NL) {
        int e = tid;
        int n = e / Lc, l = e - n * Lc;
        int lag = (l == 0) ? 1 : (l == 1) ? 5 : 21;
        int tr = t - lag;
        sfb[e] = (tr >= 0) ? biasTab[b * NL + e] : -INFINITY;
        if (tr < 0) tr = 0;
        soff[e] = ((b * Nc + n) * Tc + tr) << 8;   // * Hc
    }
    __syncthreads();

    float4 q0 = ((const float4*)sQk)[lane];
    float4 q1 = ((const float4*)sQk)[lane + 32];

    // dot phase: warp w handles e = w + 8j + 24r
#pragma unroll 1
    for (int r = 0; r < 8; r++) {
        int ebase = warp + 24 * r;
        float4 v0[3], v1[3];
        float acc[3];
#pragma unroll
        for (int j = 0; j < 3; j++) {
            const float4* row = (const float4*)(peer + (size_t)(unsigned)soff[ebase + 8 * j]);
            v0[j] = row[lane];
            v1[j] = row[lane + 32];
        }
#pragma unroll
        for (int j = 0; j < 3; j++) {
            acc[j] = v0[j].x*q0.x + v0[j].y*q0.y + v0[j].z*q0.z + v0[j].w*q0.w
                   + v1[j].x*q1.x + v1[j].y*q1.y + v1[j].z*q1.z + v1[j].w*q1.w;
        }
#pragma unroll
        for (int s = 16; s; s >>= 1) {
            acc[0] += __shfl_xor_sync(0xffffffffu, acc[0], s);
            acc[1] += __shfl_xor_sync(0xffffffffu, acc[1], s);
            acc[2] += __shfl_xor_sync(0xffffffffu, acc[2], s);
        }
        if (lane == 0) {
#pragma unroll
            for (int j = 0; j < 3; j++)
                sev[warp][r * 3 + j] = acc[j] + sfb[ebase + 8 * j];
        }
    }
    __syncwarp();

    // per-warp top-8 via rank counting (lanes 0..23, each ranks one slot)
    if (lane < 24) {
        float v = sev[warp][lane];
        int e = warp + 8 * (lane % 3) + 24 * (lane / 3);
        int rank = 0;
#pragma unroll
        for (int j = 0; j < 24; j++) {
            float vj = sev[warp][j];
            int ej = warp + 8 * (j % 3) + 24 * (j / 3);
            if (vj > v || (vj == v && ej < e)) rank++;
        }
        if (rank < 8) { scv[warp * 8 + rank] = v; scix[warp * 8 + rank] = e; }
    }
    __syncthreads();

    // merge 64 candidates -> global top-8 via rank counting
    if (tid < 64) {
        float v = scv[tid]; int e = scix[tid];
        int rank = 0;
#pragma unroll 8
        for (int j = 0; j < 64; j++) {
            float vj = scv[j]; int ej = scix[j];
            if (vj > v || (vj == v && ej < e)) rank++;
        }
        if (rank < KTOP) { swv[rank] = v; sidx[rank] = e; }
    }
    __syncthreads();

    // softmax over top-8, computed redundantly by every thread
    float w[KTOP];
    {
        float vs[KTOP]; float m = -INFINITY;
        bool allinf = (swv[0] == -INFINITY);   // top-1 is the max
#pragma unroll
        for (int r = 0; r < KTOP; r++) {
            float v = swv[r];
            vs[r] = (v == -INFINITY) ? -1e9f : v;
            m = fmaxf(m, vs[r]);
        }
        float z = 0.f;
#pragma unroll
        for (int r = 0; r < KTOP; r++) { w[r] = expf(vs[r] - m); z += w[r]; }
        float invz = allinf ? 0.f : 1.f / z;
#pragma unroll
        for (int r = 0; r < KTOP; r++) w[r] *= invz;
        if (tid == 0) wsum[bt] = allinf ? 0.f : 1.f;
    }

    // weighted delta sum: sum_k w_k * (peer[b,n_k,t,h] - peer[b,n_k,t-lag_k,h])
    const int lags[3] = {1, 5, 21};
    float acc = 0.f;
#pragma unroll
    for (int r = 0; r < KTOP; r++) {
        float wr = w[r];
        if (wr != 0.f) {
            int e = sidx[r];
            int n = e / Lc, l = e - n * Lc;
            int lag = lags[l];
            const float* base = peer + (((size_t)b * Nc + n) * Tc + t) * Hc;
            acc += wr * (base[tid] - base[tid - lag * Hc]);
        }
    }
    dsum[(size_t)bt * Hc + tid] = acc;
}

// ---------------- layernorm, one block per row ----------------
__global__ void ln_kernel(const float* __restrict__ x, const float* __restrict__ g,
                          const float* __restrict__ bta, float* __restrict__ out)
{
    int row = blockIdx.x, tid = threadIdx.x;
    __shared__ float red1[8];
    __shared__ float red2[8];
    __shared__ float s_mu, s_var;

    float v = x[(size_t)row * Hc + tid];
    float s = v;
#pragma unroll
    for (int o = 16; o; o >>= 1) s += __shfl_xor_sync(0xffffffffu, s, o);
    if ((tid & 31) == 0) red1[tid >> 5] = s;
    __syncthreads();
    if (tid < 32) {
        float t2 = (tid < 8) ? red1[tid] : 0.f;
#pragma unroll
        for (int o = 4; o; o >>= 1) t2 += __shfl_xor_sync(0xffffffffu, t2, o);
        if (tid == 0) s_mu = t2 * (1.f / Hc);
    }
    __syncthreads();
    float mu = s_mu;
    float d = v - mu;
    float s2 = d * d;
#pragma unroll
    for (int o = 16; o; o >>= 1) s2 += __shfl_xor_sync(0xffffffffu, s2, o);
    if ((tid & 31) == 0) red2[tid >> 5] = s2;
    __syncthreads();
    if (tid < 32) {
        float t2 = (tid < 8) ? red2[tid] : 0.f;
#pragma unroll
        for (int o = 4; o; o >>= 1) t2 += __shfl_xor_sync(0xffffffffu, t2, o);
        if (tid == 0) s_var = t2 * (1.f / Hc);
    }
    __syncthreads();
    out[(size_t)row * Hc + tid] = d * rsqrtf(s_var + 1e-5f) * g[tid] + bta[tid];
}

// ---------------- launch ----------------
extern "C" void kernel_launch(void* const* d_in, const int* in_sizes, int n_in,
                              void* d_out, int out_size)
{
    const float* target_h = (const float*)d_in[0];
    const float* peer_h   = (const float*)d_in[1];
    const float* wq_w = (const float*)d_in[2];
    const float* wq_b = (const float*)d_in[3];
    const float* wk_w = (const float*)d_in[4];
    // d_in[5] = wk_b: uniform logit shift, output-invariant -> unused
    const float* wv_w = (const float*)d_in[6];
    const float* wv_b = (const float*)d_in[7];
    const float* f1_w = (const float*)d_in[8];
    const float* f1_b = (const float*)d_in[9];
    const float* f2_w = (const float*)d_in[10];
    const float* f2_b = (const float*)d_in[11];
    const float* ln_g = (const float*)d_in[12];
    const float* ln_b = (const float*)d_in[13];
    const float* alpha = (const float*)d_in[14];
    const float* lrs   = (const float*)d_in[15];
    const void* peer_mask = (const void*)d_in[16];
    const void* rmask     = (const void*)d_in[17];
    const int* target_id = (const int*)d_in[18];
    const int* peer_id   = (const int*)d_in[19];
    float* out = (float*)d_out;

    float *pA, *pc, *pQk, *pdsum, *pwsum, *plly, *ph1, *px, *pbias;
    cudaGetSymbolAddress((void**)&pA,    g_A);
    cudaGetSymbolAddress((void**)&pc,    g_c);
    cudaGetSymbolAddress((void**)&pQk,   g_Qk);
    cudaGetSymbolAddress((void**)&pdsum, g_dsum);
    cudaGetSymbolAddress((void**)&pwsum, g_wsum);
    cudaGetSymbolAddress((void**)&plly,  g_lly);
    cudaGetSymbolAddress((void**)&ph1,   g_h1);
    cudaGetSymbolAddress((void**)&px,    g_x);
    cudaGetSymbolAddress((void**)&pbias, g_bias);

    const float s = 0.0625f; // 1/sqrt(256)

    // 1: A = s * wq_w^T @ wk_w ; fused c = s * wq_b @ wk_w ; aux row = detprep
    gemm32<true, false, false, false, false, false, true>
        <<<dim3(Hc / 64, Hc / 32 + 1), 128>>>(wq_w, wk_w, nullptr, nullptr, nullptr, pA,
                                              wq_b, pc, Hc, Hc, Hc, s,
                                              lrs, peer_mask, rmask, target_id, peer_id,
                                              alpha, pbias);

    // 2: Qk = X @ A + c
    gemm32<false, false, false, true, false, false, false>
        <<<dim3(Hc / 64, BT / 32), 128>>>(target_h, pA, pc, nullptr, nullptr, pQk,
                                          nullptr, nullptr, BT, Hc, Hc, 1.f,
                                          nullptr, nullptr, nullptr, nullptr, nullptr,
                                          nullptr, nullptr);

    // 3: logits + top-8 + weighted delta sum
    logits_kernel<<<BT, 256>>>(peer_h, pbias, pQk, pdsum, pwsum);

    // 4: ll_y = dsum @ wv_w^T + wsum*wv_b   (ncu profile slot)
    gemm32<false, true, false, true, true, false, false>
        <<<dim3(Hc / 64, BT / 32), 128>>>(pdsum, wv_w, wv_b, pwsum, nullptr, plly,
                                          nullptr, nullptr, BT, Hc, Hc, 1.f,
                                          nullptr, nullptr, nullptr, nullptr, nullptr,
                                          nullptr, nullptr);

    // 5: h1 = elu(ll_y @ f1_w^T + f1_b)
    gemm32<false, true, true, true, false, false, false>
        <<<dim3(Hc / 64, BT / 32), 128>>>(plly, f1_w, f1_b, nullptr, nullptr, ph1,
                                          nullptr, nullptr, BT, Hc, Hc, 1.f,
                                          nullptr, nullptr, nullptr, nullptr, nullptr,
                                          nullptr, nullptr);

    // 6: x = ll_y + h1 @ f2_w^T + f2_b
    gemm32<false, true, false, true, false, true, false>
        <<<dim3(Hc / 64, BT / 32), 128>>>(ph1, f2_w, f2_b, nullptr, plly, px,
                                          nullptr, nullptr, BT, Hc, Hc, 1.f,
                                          nullptr, nullptr, nullptr, nullptr, nullptr,
                                          nullptr, nullptr);

    // 7: out = LN(x) * g + b
    ln_kernel<<<BT, Hc>>>(px, ln_g, ln_b, out);
}

// round 14
// speedup vs baseline: 1.1398x; 1.0024x over previous
#include <cuda_runtime.h>
#include <math.h>
#include <stdint.h>

#define Bc 4
#define Nc 64
#define Tc 384
#define Hc 256
#define Lc 3
#define NUc 500
#define KTOP 8
#define BT (Bc*Tc)   // 1536
#define NL (Nc*Lc)   // 192

// ---------------- scratch (device globals; no allocation allowed) ----------------
__device__ __align__(16) float g_A   [Hc*Hc];
__device__ __align__(16) float g_c   [Hc];
__device__ __align__(16) float g_Qk  [BT*Hc];
__device__ __align__(16) float g_dsum[BT*Hc];
__device__             float g_wsum[BT];
__device__ __align__(16) float g_lly [BT*Hc];
__device__ __align__(16) float g_h1  [BT*Hc];
__device__ __align__(16) float g_x   [BT*Hc];
__device__ __align__(16) float g_bias[Bc*NL];

__device__ __forceinline__ bool mask_read(const void* m, size_t i, int is_byte)
{
    if (is_byte) return ((const unsigned char*)m)[i] != 0;
    return ((const unsigned int*)m)[i] != 0u;   // int32 AND float32 (bit-pattern nonzero)
}

// ---------------- detprep (device fn, runs as aux block of gemmA) ----------------
__device__ void detprep_device(const float* __restrict__ lrs,
                               const void* __restrict__ pm, const void* __restrict__ rm,
                               const int* __restrict__ target_id,
                               const int* __restrict__ peer_id,
                               const float* __restrict__ alpha_p,
                               float* __restrict__ biasTab)
{
    __shared__ unsigned s_g, s_o;
    if (threadIdx.x == 0) { s_g = 0u; s_o = 0u; }
    __syncthreads();
    const uint4* rm16 = (const uint4*)rm;
    const int n16 = 16384;  // scan first 256 KB of rank mask
    unsigned gt1 = 0u, off = 0u;
    for (int i = threadIdx.x; i < n16; i += blockDim.x) {
        uint4 v = rm16[i];
        unsigned w = v.x | v.y | v.z | v.w;
        gt1 |= w & 0xFEFEFEFEu;   // any byte value > 1 -> float32 words
        off |= w & 0xFFFFFF00u;   // nonzero byte at idx%4 != 0 -> uint8
    }
#pragma unroll
    for (int s = 16; s; s >>= 1) {
        gt1 |= __shfl_xor_sync(0xffffffffu, gt1, s);
        off |= __shfl_xor_sync(0xffffffffu, off, s);
    }
    if ((threadIdx.x & 31) == 0) {
        if (gt1) atomicOr(&s_g, 1u);
        if (off) atomicOr(&s_o, 1u);
    }
    __syncthreads();
    int ib = (s_g == 0u && s_o != 0u) ? 1 : 0;

    float alpha = *alpha_p;
    for (int idx = threadIdx.x; idx < Bc * NL; idx += blockDim.x) {
        int b = idx / NL, e = idx - b * NL;
        int n = e / Lc, l = e - n * Lc;
        int tgt = target_id[b], pid = peer_id[b * Nc + n];
        size_t offr = ((size_t)l * NUc + pid) * NUc + tgt;
        bool valid = mask_read(pm, b * Nc + n, ib) && mask_read(rm, offr, ib);
        biasTab[idx] = valid ? alpha * lrs[offr] : -INFINITY;
    }
}

// ---------------- 32x64x16 fp32 GEMM, 128 threads, double-buffered smem ----------
// C[M,N] = scale * op(A)[M,K] @ op(B)[K,N] (+bias[n]*rowscale[m]) (+add[m,n]) (ELU)
// AUX (A-gemm only): blockIdx.y==0 blocks also emit cvec; the extra grid.y row runs detprep.
template<bool A_T, bool B_T, bool DO_ELU, bool HAS_BIAS, bool HAS_SCALE, bool HAS_ADD, bool AUX>
__global__ void gemm32(const float* __restrict__ A, const float* __restrict__ Bm,
                       const float* __restrict__ bias, const float* __restrict__ rowscale,
                       const float* __restrict__ addm, float* __restrict__ C,
                       const float* __restrict__ cvec_in, float* __restrict__ cvec_out,
                       int M, int N, int K, float scale,
                       const float* lrs, const void* pm, const void* rm,
                       const int* target_id, const int* peer_id,
                       const float* alpha_p, float* biasTab)
{
    if (AUX && blockIdx.y == gridDim.y - 1) {
        if (blockIdx.x == 0)
            detprep_device(lrs, pm, rm, target_id, peer_id, alpha_p, biasTab);
        return;
    }

    const int BM = 32, BN = 64, BK = 16;
    __shared__ __align__(16) float As[2][BK][BM + 4];
    __shared__ __align__(16) float Bs[2][BK][BN + 4];

    int tid = threadIdx.x;                 // 128 threads
    int m0 = blockIdx.y * BM, n0 = blockIdx.x * BN;
    int tx = tid & 15, ty = tid >> 4;      // ty in 0..7

    int aI0, aI1, bI0, bI1;
    if (!A_T) { aI0 = tid >> 2; aI1 = (tid & 3) << 2; }
    else      { aI0 = tid >> 3; aI1 = (tid & 7) << 2; }
    if (!B_T) { bI0 = tid >> 4; bI1 = (tid & 15) << 2; }
    else      { bI0 = tid >> 2; bI1 = (tid & 3) << 2; }

    float acc[4][4];
#pragma unroll
    for (int i = 0; i < 4; i++)
#pragma unroll
        for (int j = 0; j < 4; j++) acc[i][j] = 0.f;

    float cacc[4] = {0.f, 0.f, 0.f, 0.f};
    const bool do_cvec = AUX && (blockIdx.y == 0) && (ty == 0);

    float4 va, vb0, vb1;
    if (!A_T) va = *(const float4*)&A[(size_t)(m0 + aI0) * K + aI1];
    else      va = *(const float4*)&A[(size_t)aI0 * M + m0 + aI1];
    if (!B_T) { vb0 = *(const float4*)&Bm[(size_t)bI0 * N + n0 + bI1];
                vb1 = *(const float4*)&Bm[(size_t)(bI0 + 8) * N + n0 + bI1]; }
    else      { vb0 = *(const float4*)&Bm[(size_t)(n0 + bI0) * K + bI1];
                vb1 = *(const float4*)&Bm[(size_t)(n0 + bI0 + 32) * K + bI1]; }
    if (!A_T) { As[0][aI1+0][aI0]=va.x; As[0][aI1+1][aI0]=va.y; As[0][aI1+2][aI0]=va.z; As[0][aI1+3][aI0]=va.w; }
    else      { *(float4*)&As[0][aI0][aI1] = va; }
    if (!B_T) { *(float4*)&Bs[0][bI0][bI1] = vb0; *(float4*)&Bs[0][bI0+8][bI1] = vb1; }
    else      { Bs[0][bI1+0][bI0]=vb0.x; Bs[0][bI1+1][bI0]=vb0.y; Bs[0][bI1+2][bI0]=vb0.z; Bs[0][bI1+3][bI0]=vb0.w;
                Bs[0][bI1+0][bI0+32]=vb1.x; Bs[0][bI1+1][bI0+32]=vb1.y; Bs[0][bI1+2][bI0+32]=vb1.z; Bs[0][bI1+3][bI0+32]=vb1.w; }
    __syncthreads();

    int buf = 0;
    for (int k0 = 0; k0 < K; k0 += BK) {
        bool has_next = (k0 + BK < K);
        if (has_next) {
            int kn = k0 + BK;
            if (!A_T) va = *(const float4*)&A[(size_t)(m0 + aI0) * K + kn + aI1];
            else      va = *(const float4*)&A[(size_t)(kn + aI0) * M + m0 + aI1];
            if (!B_T) { vb0 = *(const float4*)&Bm[(size_t)(kn + bI0) * N + n0 + bI1];
                        vb1 = *(const float4*)&Bm[(size_t)(kn + bI0 + 8) * N + n0 + bI1]; }
            else      { vb0 = *(const float4*)&Bm[(size_t)(n0 + bI0) * K + kn + bI1];
                        vb1 = *(const float4*)&Bm[(size_t)(n0 + bI0 + 32) * K + kn + bI1]; }
        }
#pragma unroll
        for (int kk = 0; kk < BK; kk++) {
            float4 a4 = *(const float4*)&As[buf][kk][ty << 2];
            float4 b4 = *(const float4*)&Bs[buf][kk][tx << 2];
            float a[4] = {a4.x, a4.y, a4.z, a4.w};
            float b[4] = {b4.x, b4.y, b4.z, b4.w};
#pragma unroll
            for (int i = 0; i < 4; i++)
#pragma unroll
                for (int j = 0; j < 4; j++) acc[i][j] += a[i] * b[j];
            if (AUX) {
                if (do_cvec) {
                    float wb = __ldg(&cvec_in[k0 + kk]);
                    cacc[0] += wb * b4.x; cacc[1] += wb * b4.y;
                    cacc[2] += wb * b4.z; cacc[3] += wb * b4.w;
                }
            }
        }
        if (has_next) {
            int s = buf ^ 1;
            if (!A_T) { As[s][aI1+0][aI0]=va.x; As[s][aI1+1][aI0]=va.y; As[s][aI1+2][aI0]=va.z; As[s][aI1+3][aI0]=va.w; }
            else      { *(float4*)&As[s][aI0][aI1] = va; }
            if (!B_T) { *(float4*)&Bs[s][bI0][bI1] = vb0; *(float4*)&Bs[s][bI0+8][bI1] = vb1; }
            else      { Bs[s][bI1+0][bI0]=vb0.x; Bs[s][bI1+1][bI0]=vb0.y; Bs[s][bI1+2][bI0]=vb0.z; Bs[s][bI1+3][bI0]=vb0.w;
                        Bs[s][bI1+0][bI0+32]=vb1.x; Bs[s][bI1+1][bI0+32]=vb1.y; Bs[s][bI1+2][bI0+32]=vb1.z; Bs[s][bI1+3][bI0+32]=vb1.w; }
        }
        __syncthreads();
        buf ^= 1;
    }

    if (AUX) {
        if (do_cvec) {
            float4 cv = make_float4(cacc[0]*scale, cacc[1]*scale, cacc[2]*scale, cacc[3]*scale);
            *(float4*)&cvec_out[n0 + (tx << 2)] = cv;
        }
    }

#pragma unroll
    for (int i = 0; i < 4; i++) {
        int m = m0 + (ty << 2) + i;
        float rs = 1.f;
        if (HAS_SCALE) rs = rowscale[m];
        float4 outv;
        float* po = (float*)&outv;
#pragma unroll
        for (int j = 0; j < 4; j++) {
            int n = n0 + (tx << 2) + j;
            float v = acc[i][j] * scale;
            if (HAS_BIAS) v += bias[n] * rs;
            if (HAS_ADD)  v += addm[(size_t)m * N + n];
            if (DO_ELU)   v = (v > 0.f) ? v : expm1f(v);
            po[j] = v;
        }
        *(float4*)&C[(size_t)m * N + n0 + (tx << 2)] = outv;
    }
}

// ---------------- logits + parallel rank top-8 + weighted delta-sum --------------
// Per-(b,t)-invariant row offsets + time-folded bias precomputed into smem.
__global__ void logits_kernel(const float* __restrict__ peer,
                              const float* __restrict__ biasTab,
                              const float* __restrict__ Qk,
                              float* __restrict__ dsum,
                              float* __restrict__ wsum)
{
    int bt = blockIdx.x;
    int b = bt / Tc, t = bt - b * Tc;
    int tid = threadIdx.x, lane = tid & 31, warp = tid >> 5;

    __shared__ __align__(16) float sQk[Hc];
    __shared__ int   soff[NL];       // element offset of lagged row start
    __shared__ float sfb [NL];       // bias folded with time-validity
    __shared__ float sev[8][24];     // per-warp e-values
    __shared__ float scv[64];        // 8 warps x top-8 candidate values
    __shared__ int   scix[64];       // candidate flat-e indices
    __shared__ float swv[KTOP];      // global top-8 raw values
    __shared__ int   sidx[KTOP];

    if (tid < 64) ((float4*)sQk)[tid] = ((const float4*)(Qk + (size_t)bt * Hc))[tid];
    if (tid < NL) {
        int e = tid;
        int n = e / Lc, l = e - n * Lc;
        int lag = (l == 0) ? 1 : (l == 1) ? 5 : 21;
        int tr = t - lag;
        sfb[e] = (tr >= 0) ? biasTab[b * NL + e] : -INFINITY;
        if (tr < 0) tr = 0;
        soff[e] = ((b * Nc + n) * Tc + tr) << 8;   // * Hc
    }
    __syncthreads();

    float4 q0 = ((const float4*)sQk)[lane];
    float4 q1 = ((const float4*)sQk)[lane + 32];

    // dot phase: warp w handles e = w + 8j + 24r
#pragma unroll 1
    for (int r = 0; r < 8; r++) {
        int ebase = warp + 24 * r;
        float4 v0[3], v1[3];
        float acc[3];
#pragma unroll
        for (int j = 0; j < 3; j++) {
            const float4* row = (const float4*)(peer + (size_t)(unsigned)soff[ebase + 8 * j]);
            v0[j] = row[lane];
            v1[j] = row[lane + 32];
        }
#pragma unroll
        for (int j = 0; j < 3; j++) {
            acc[j] = v0[j].x*q0.x + v0[j].y*q0.y + v0[j].z*q0.z + v0[j].w*q0.w
                   + v1[j].x*q1.x + v1[j].y*q1.y + v1[j].z*q1.z + v1[j].w*q1.w;
        }
#pragma unroll
        for (int s = 16; s; s >>= 1) {
            acc[0] += __shfl_xor_sync(0xffffffffu, acc[0], s);
            acc[1] += __shfl_xor_sync(0xffffffffu, acc[1], s);
            acc[2] += __shfl_xor_sync(0xffffffffu, acc[2], s);
        }
        if (lane == 0) {
#pragma unroll
            for (int j = 0; j < 3; j++)
                sev[warp][r * 3 + j] = acc[j] + sfb[ebase + 8 * j];
        }
    }
    __syncwarp();

    // per-warp top-8 via rank counting (lanes 0..23, each ranks one slot)
    if (lane < 24) {
        float v = sev[warp][lane];
        int e = warp + 8 * (lane % 3) + 24 * (lane / 3);
        int rank = 0;
#pragma unroll
        for (int j = 0; j < 24; j++) {
            float vj = sev[warp][j];
            int ej = warp + 8 * (j % 3) + 24 * (j / 3);
            if (vj > v || (vj == v && ej < e)) rank++;
        }
        if (rank < 8) { scv[warp * 8 + rank] = v; scix[warp * 8 + rank] = e; }
    }
    __syncthreads();

    // merge 64 candidates -> global top-8 via rank counting
    if (tid < 64) {
        float v = scv[tid]; int e = scix[tid];
        int rank = 0;
#pragma unroll 8
        for (int j = 0; j < 64; j++) {
            float vj = scv[j]; int ej = scix[j];
            if (vj > v || (vj == v && ej < e)) rank++;
        }
        if (rank < KTOP) { swv[rank] = v; sidx[rank] = e; }
    }
    __syncthreads();

    // softmax over top-8, computed redundantly by every thread
    float w[KTOP];
    {
        float vs[KTOP]; float m = -INFINITY;
        bool allinf = (swv[0] == -INFINITY);   // top-1 is the max
#pragma unroll
        for (int r = 0; r < KTOP; r++) {
            float v = swv[r];
            vs[r] = (v == -INFINITY) ? -1e9f : v;
            m = fmaxf(m, vs[r]);
        }
        float z = 0.f;
#pragma unroll
        for (int r = 0; r < KTOP; r++) { w[r] = expf(vs[r] - m); z += w[r]; }
        float invz = allinf ? 0.f : 1.f / z;
#pragma unroll
        for (int r = 0; r < KTOP; r++) w[r] *= invz;
        if (tid == 0) wsum[bt] = allinf ? 0.f : 1.f;
    }

    // weighted delta sum: sum_k w_k * (peer[b,n_k,t,h] - peer[b,n_k,t-lag_k,h])
    const int lags[3] = {1, 5, 21};
    float acc = 0.f;
#pragma unroll
    for (int r = 0; r < KTOP; r++) {
        float wr = w[r];
        if (wr != 0.f) {
            int e = sidx[r];
            int n = e / Lc, l = e - n * Lc;
            int lag = lags[l];
            const float* base = peer + (((size_t)b * Nc + n) * Tc + t) * Hc;
            acc += wr * (base[tid] - base[tid - lag * Hc]);
        }
    }
    dsum[(size_t)bt * Hc + tid] = acc;
}

// ---------------- layernorm, one block per row ----------------
__global__ void ln_kernel(const float* __restrict__ x, const float* __restrict__ g,
                          const float* __restrict__ bta, float* __restrict__ out)
{
    int row = blockIdx.x, tid = threadIdx.x;
    __shared__ float red1[8];
    __shared__ float red2[8];
    __shared__ float s_mu, s_var;

    float v = x[(size_t)row * Hc + tid];
    float s = v;
#pragma unroll
    for (int o = 16; o; o >>= 1) s += __shfl_xor_sync(0xffffffffu, s, o);
    if ((tid & 31) == 0) red1[tid >> 5] = s;
    __syncthreads();
    if (tid < 32) {
        float t2 = (tid < 8) ? red1[tid] : 0.f;
#pragma unroll
        for (int o = 4; o; o >>= 1) t2 += __shfl_xor_sync(0xffffffffu, t2, o);
        if (tid == 0) s_mu = t2 * (1.f / Hc);
    }
    __syncthreads();
    float mu = s_mu;
    float d = v - mu;
    float s2 = d * d;
#pragma unroll
    for (int o = 16; o; o >>= 1) s2 += __shfl_xor_sync(0xffffffffu, s2, o);
    if ((tid & 31) == 0) red2[tid >> 5] = s2;
    __syncthreads();
    if (tid < 32) {
        float t2 = (tid < 8) ? red2[tid] : 0.f;
#pragma unroll
        for (int o = 4; o; o >>= 1) t2 += __shfl_xor_sync(0xffffffffu, t2, o);
        if (tid == 0) s_var = t2 * (1.f / Hc);
    }
    __syncthreads();
    out[(size_t)row * Hc + tid] = d * rsqrtf(s_var + 1e-5f) * g[tid] + bta[tid];
}

// ---------------- launch ----------------
extern "C" void kernel_launch(void* const* d_in, const int* in_sizes, int n_in,
                              void* d_out, int out_size)
{
    const float* target_h = (const float*)d_in[0];
    const float* peer_h   = (const float*)d_in[1];
    const float* wq_w = (const float*)d_in[2];
    const float* wq_b = (const float*)d_in[3];
    const float* wk_w = (const float*)d_in[4];
    // d_in[5] = wk_b: uniform logit shift, output-invariant -> unused
    const float* wv_w = (const float*)d_in[6];
    const float* wv_b = (const float*)d_in[7];
    const float* f1_w = (const float*)d_in[8];
    const float* f1_b = (const float*)d_in[9];
    const float* f2_w = (const float*)d_in[10];
    const float* f2_b = (const float*)d_in[11];
    const float* ln_g = (const float*)d_in[12];
    const float* ln_b = (const float*)d_in[13];
    const float* alpha = (const float*)d_in[14];
    const float* lrs   = (const float*)d_in[15];
    const void* peer_mask = (const void*)d_in[16];
    const void* rmask     = (const void*)d_in[17];
    const int* target_id = (const int*)d_in[18];
    const int* peer_id   = (const int*)d_in[19];
    float* out = (float*)d_out;

    float *pA, *pc, *pQk, *pdsum, *pwsum, *plly, *ph1, *px, *pbias;
    cudaGetSymbolAddress((void**)&pA,    g_A);
    cudaGetSymbolAddress((void**)&pc,    g_c);
    cudaGetSymbolAddress((void**)&pQk,   g_Qk);
    cudaGetSymbolAddress((void**)&pdsum, g_dsum);
    cudaGetSymbolAddress((void**)&pwsum, g_wsum);
    cudaGetSymbolAddress((void**)&plly,  g_lly);
    cudaGetSymbolAddress((void**)&ph1,   g_h1);
    cudaGetSymbolAddress((void**)&px,    g_x);
    cudaGetSymbolAddress((void**)&pbias, g_bias);

    const float s = 0.0625f; // 1/sqrt(256)

    // 1: A = s * wq_w^T @ wk_w ; fused c = s * wq_b @ wk_w ; aux row = detprep
    gemm32<true, false, false, false, false, false, true>
        <<<dim3(Hc / 64, Hc / 32 + 1), 128>>>(wq_w, wk_w, nullptr, nullptr, nullptr, pA,
                                              wq_b, pc, Hc, Hc, Hc, s,
                                              lrs, peer_mask, rmask, target_id, peer_id,
                                              alpha, pbias);

    // 2: Qk = X @ A + c
    gemm32<false, false, false, true, false, false, false>
        <<<dim3(Hc / 64, BT / 32), 128>>>(target_h, pA, pc, nullptr, nullptr, pQk,
                                          nullptr, nullptr, BT, Hc, Hc, 1.f,
                                          nullptr, nullptr, nullptr, nullptr, nullptr,
                                          nullptr, nullptr);

    // 3: logits + top-8 + weighted delta sum
    logits_kernel<<<BT, 256>>>(peer_h, pbias, pQk, pdsum, pwsum);

    // 4: ll_y = dsum @ wv_w^T + wsum*wv_b   (ncu profile slot)
    gemm32<false, true, false, true, true, false, false>
        <<<dim3(Hc / 64, BT / 32), 128>>>(pdsum, wv_w, wv_b, pwsum, nullptr, plly,
                                          nullptr, nullptr, BT, Hc, Hc, 1.f,
                                          nullptr, nullptr, nullptr, nullptr, nullptr,
                                          nullptr, nullptr);

    // 5: h1 = elu(ll_y @ f1_w^T + f1_b)
    gemm32<false, true, true, true, false, false, false>
        <<<dim3(Hc / 64, BT / 32), 128>>>(plly, f1_w, f1_b, nullptr, nullptr, ph1,
                                          nullptr, nullptr, BT, Hc, Hc, 1.f,
                                          nullptr, nullptr, nullptr, nullptr, nullptr,
                                          nullptr, nullptr);

    // 6: x = ll_y + h1 @ f2_w^T + f2_b
    gemm32<false, true, false, true, false, true, false>
        <<<dim3(Hc / 64, BT / 32), 128>>>(ph1, f2_w, f2_b, nullptr, plly, px,
                                          nullptr, nullptr, BT, Hc, Hc, 1.f,
                                          nullptr, nullptr, nullptr, nullptr, nullptr,
                                          nullptr, nullptr);

    // 7: out = LN(x) * g + b
    ln_kernel<<<BT, Hc>>>(px, ln_g, ln_b, out);
}